// round 8
// baseline (speedup 1.0000x reference)
#include <cuda_runtime.h>
#include <cuda_bf16.h>
#include <cstdint>

// ---------------------------------------------------------------------------
// GCN: 4x GCNConv(128->128) + output linear(128->128), N=100000, E=1600000.
// Round 8: GEMM occupancy push — 512 threads/CTA (16 warps, 4x4 layout),
// 96KB smem, 2 CTAs/SM -> 50% occ (was 25%). Tensor pipe had 4x headroom.
// ---------------------------------------------------------------------------

#define NMAX 100096
#define EMAX 1600000
#define FDIM 128
#define SCAN_B 1024
#define MAXBLK 128
#define BM 64
#define GT 512   // GEMM threads per CTA

__device__ float g_t[(size_t)NMAX * FDIM];
__device__ float g_h[(size_t)NMAX * FDIM];
__device__ float g_deg[NMAX];
__device__ float g_dinv[NMAX];
__device__ int   g_cnt[NMAX];
__device__ int   g_rowptr[NMAX + 1];
__device__ int   g_cursor[NMAX];
__device__ int   g_srow[EMAX];
__device__ float g_snorm[EMAX];
__device__ int   g_bsum[MAXBLK];
__device__ int   g_boffs[MAXBLK];
__device__ __align__(16) __nv_bfloat16 g_whi[5 * 16384];
__device__ __align__(16) __nv_bfloat16 g_wlo[5 * 16384];

// ---------------- helpers ----------------

__device__ __forceinline__ uint32_t smem_u32(const void* p) {
    uint32_t a;
    asm("{ .reg .u64 t; cvta.to.shared.u64 t, %1; cvt.u32.u64 %0, t; }" : "=r"(a) : "l"(p));
    return a;
}

__device__ __forceinline__ void ldsm4(uint32_t& r0, uint32_t& r1, uint32_t& r2,
                                      uint32_t& r3, uint32_t addr) {
    asm volatile("ldmatrix.sync.aligned.m8n8.x4.shared.b16 {%0,%1,%2,%3}, [%4];"
                 : "=r"(r0), "=r"(r1), "=r"(r2), "=r"(r3) : "r"(addr));
}

__device__ __forceinline__ void mma16816(float* c, const uint32_t* a,
                                         uint32_t b0, uint32_t b1) {
    asm volatile(
        "mma.sync.aligned.m16n8k16.row.col.f32.bf16.bf16.f32 "
        "{%0,%1,%2,%3}, {%4,%5,%6,%7}, {%8,%9}, {%0,%1,%2,%3};"
        : "+f"(c[0]), "+f"(c[1]), "+f"(c[2]), "+f"(c[3])
        : "r"(a[0]), "r"(a[1]), "r"(a[2]), "r"(a[3]), "r"(b0), "r"(b1));
}

__device__ __forceinline__ void cp16(uint32_t dst, const void* src) {
    asm volatile("cp.async.ca.shared.global [%0], [%1], 16;" :: "r"(dst), "l"(src));
}

// XOR-swizzled: 256B rows (128 bf16); addr(r,k) = r*256 + ((k>>3)^(r&7))*16 + (k&7)*2
__device__ __forceinline__ uint32_t swz(int r, int k) {
    return (uint32_t)((r << 8) + ((((k >> 3) ^ (r & 7)) << 4)) + ((k & 7) << 1));
}

// ---------------- degree + histogram ----------------

__global__ void k_init(float* __restrict__ deg, int* __restrict__ cnt,
                       int* __restrict__ cur, int n) {
    int i = blockIdx.x * blockDim.x + threadIdx.x;
    if (i < n) { deg[i] = 1.0f; cnt[i] = 0; cur[i] = 0; }
}

__global__ void k_deg_hist(const int* __restrict__ col, const float* __restrict__ ew,
                           float* __restrict__ deg, int* __restrict__ cnt, int E) {
    int e = blockIdx.x * blockDim.x + threadIdx.x;
    if (e < E) {
        int c = col[e];
        atomicAdd(&deg[c], ew[e]);
        atomicAdd(&cnt[c], 1);
    }
}

__global__ void k_dinv(const float* __restrict__ deg, float* __restrict__ dinv, int n) {
    int i = blockIdx.x * blockDim.x + threadIdx.x;
    if (i < n) {
        float d = deg[i];
        dinv[i] = (d > 0.0f) ? rsqrtf(d) : 0.0f;
    }
}

// ---------------- 3-phase scan ----------------

__global__ void __launch_bounds__(SCAN_B) k_scan_local(
    const int* __restrict__ cnt, int* __restrict__ rowptr,
    int* __restrict__ bsum, int n)
{
    __shared__ int s[SCAN_B];
    const int tid = threadIdx.x;
    const int i = blockIdx.x * SCAN_B + tid;
    int v = (i < n) ? cnt[i] : 0;
    s[tid] = v;
    __syncthreads();
#pragma unroll
    for (int ofs = 1; ofs < SCAN_B; ofs <<= 1) {
        int t = (tid >= ofs) ? s[tid - ofs] : 0;
        __syncthreads();
        s[tid] += t;
        __syncthreads();
    }
    if (i < n) rowptr[i] = s[tid] - v;
    if (tid == SCAN_B - 1) bsum[blockIdx.x] = s[tid];
}

__global__ void __launch_bounds__(MAXBLK) k_scan_mid(
    const int* __restrict__ bsum, int* __restrict__ boffs, int nb)
{
    __shared__ int s[MAXBLK];
    const int tid = threadIdx.x;
    int v = (tid < nb) ? bsum[tid] : 0;
    s[tid] = v;
    __syncthreads();
#pragma unroll
    for (int ofs = 1; ofs < MAXBLK; ofs <<= 1) {
        int t = (tid >= ofs) ? s[tid - ofs] : 0;
        __syncthreads();
        s[tid] += t;
        __syncthreads();
    }
    if (tid < nb) boffs[tid] = s[tid] - v;
}

__global__ void __launch_bounds__(SCAN_B) k_scan_add(
    int* __restrict__ rowptr, const int* __restrict__ boffs, int n, int E)
{
    const int i = blockIdx.x * SCAN_B + threadIdx.x;
    if (i < n) rowptr[i] += boffs[blockIdx.x];
    if (i == 0) rowptr[n] = E;
}

// ---------------- counting-sort fill ----------------

__global__ void k_fill(const int* __restrict__ row, const int* __restrict__ col,
                       const float* __restrict__ ew, const float* __restrict__ dinv,
                       const int* __restrict__ rowptr, int* __restrict__ cur,
                       int* __restrict__ srow, float* __restrict__ snorm, int E) {
    int e = blockIdx.x * blockDim.x + threadIdx.x;
    if (e >= E) return;
    int r = row[e];
    int c = col[e];
    int pos = rowptr[c] + atomicAdd(&cur[c], 1);
    srow[pos] = r;
    snorm[pos] = dinv[r] * ew[e] * dinv[c];
}

// ---------------- weight prep ----------------

__global__ void k_wprep(const float* __restrict__ W, __nv_bfloat16* __restrict__ dhi,
                        __nv_bfloat16* __restrict__ dlo) {
    int idx = blockIdx.x * blockDim.x + threadIdx.x;
    if (idx >= 16384) return;
    int n = idx >> 7, k = idx & 127;
    float w = W[k * 128 + n];                 // B[n][k] = W[k][n]
    __nv_bfloat16 hi = __float2bfloat16(w);
    __nv_bfloat16 lo = __float2bfloat16(w - __bfloat162float(hi));
    dhi[n * 128 + k] = hi;
    dlo[n * 128 + k] = lo;
}

// ---------------- HMMA GEMM: C[M,128] = act(A[M,128]) @ W (+bias) ----------------
// BM=64, 512 threads, 16 warps in 4x4 (16 rows x 32 cols per warp), XOR swizzle.

__global__ void __launch_bounds__(GT, 2) k_gemm_mma(
    const float* __restrict__ A, const __nv_bfloat16* __restrict__ whi,
    const __nv_bfloat16* __restrict__ wlo, const float* __restrict__ bias,
    float* __restrict__ C, int M, int doRelu, int doBias)
{
    extern __shared__ char sm[];
    char* sAhi = sm;                  // 16KB
    char* sAlo = sm + 16384;          // 16KB
    char* sWhi = sm + 32768;          // 32KB
    char* sWlo = sm + 65536;          // 32KB

    const int tid = threadIdx.x;
    const int wid = tid >> 5;
    const int lane = tid & 31;
    const int rbase = blockIdx.x * BM;

    const uint32_t uWhi = smem_u32(sWhi);
    const uint32_t uWlo = smem_u32(sWlo);
    const uint32_t uAhi = smem_u32(sAhi);
    const uint32_t uAlo = smem_u32(sAlo);

    for (int i = tid; i < 2048; i += GT) {
        int r = i >> 4, c = i & 15;
        uint32_t doff = (uint32_t)((r << 8) + ((c ^ (r & 7)) << 4));
        cp16(uWhi + doff, whi + r * 128 + c * 8);
        cp16(uWlo + doff, wlo + r * 128 + c * 8);
    }
    asm volatile("cp.async.commit_group;" ::: "memory");

    for (int idx = tid; idx < BM * 32; idx += GT) {
        int row = idx >> 5;
        int c4 = (idx & 31) << 2;
        int grow = rbase + row;
        float4 av = make_float4(0.f, 0.f, 0.f, 0.f);
        if (grow < M)
            av = *reinterpret_cast<const float4*>(A + (size_t)grow * FDIM + c4);
        if (doRelu) {
            av.x = fmaxf(av.x, 0.f); av.y = fmaxf(av.y, 0.f);
            av.z = fmaxf(av.z, 0.f); av.w = fmaxf(av.w, 0.f);
        }
        __nv_bfloat162 h01, h23, l01, l23;
        h01.x = __float2bfloat16(av.x);
        h01.y = __float2bfloat16(av.y);
        h23.x = __float2bfloat16(av.z);
        h23.y = __float2bfloat16(av.w);
        l01.x = __float2bfloat16(av.x - __bfloat162float(h01.x));
        l01.y = __float2bfloat16(av.y - __bfloat162float(h01.y));
        l23.x = __float2bfloat16(av.z - __bfloat162float(h23.x));
        l23.y = __float2bfloat16(av.w - __bfloat162float(h23.y));
        uint32_t off = swz(row, c4);
        *reinterpret_cast<uint32_t*>(sAhi + off)     = *reinterpret_cast<uint32_t*>(&h01);
        *reinterpret_cast<uint32_t*>(sAhi + off + 4) = *reinterpret_cast<uint32_t*>(&h23);
        *reinterpret_cast<uint32_t*>(sAlo + off)     = *reinterpret_cast<uint32_t*>(&l01);
        *reinterpret_cast<uint32_t*>(sAlo + off + 4) = *reinterpret_cast<uint32_t*>(&l23);
    }
    asm volatile("cp.async.wait_group 0;" ::: "memory");
    __syncthreads();

    // 4x4 warp grid: 16 rows x 32 cols per warp
    const int warpRow = (wid & 3) * 16;
    const int warpCol = (wid >> 2) * 32;
    const int a_r = lane & 15;
    const int a_k = (lane >> 4) << 3;
    const int b_n = (lane & 7) + ((lane >> 4) << 3);
    const int b_k = ((lane >> 3) & 1) << 3;

    const uint32_t aTerm[3] = {uAhi, uAlo, uAhi};
    const uint32_t bTerm[3] = {uWhi, uWhi, uWlo};

    float c[4][4];
#pragma unroll
    for (int ni = 0; ni < 4; ni++)
#pragma unroll
        for (int q = 0; q < 4; q++) c[ni][q] = 0.0f;

    // software-pipelined over 24 (term, k-step) iterations
    uint32_t a[2][4], b0[2][4], b1[2][4];
    {
        const uint32_t ab = aTerm[0], bb = bTerm[0];
        ldsm4(a[0][0], a[0][1], a[0][2], a[0][3], ab + swz(warpRow + a_r,      a_k));
        ldsm4(b0[0][0], b0[0][1], b0[0][2], b0[0][3], bb + swz(warpCol + b_n,      b_k));
        ldsm4(b1[0][0], b1[0][1], b1[0][2], b1[0][3], bb + swz(warpCol + 16 + b_n, b_k));
    }
#pragma unroll
    for (int it = 0; it < 24; it++) {
        const int cur = it & 1, nxt = cur ^ 1;
        if (it < 23) {
            const int itn = it + 1;
            const uint32_t ab = aTerm[itn >> 3], bb = bTerm[itn >> 3];
            const int k0 = (itn & 7) << 4;
            ldsm4(a[nxt][0], a[nxt][1], a[nxt][2], a[nxt][3],
                  ab + swz(warpRow + a_r, k0 + a_k));
            ldsm4(b0[nxt][0], b0[nxt][1], b0[nxt][2], b0[nxt][3],
                  bb + swz(warpCol + b_n,      k0 + b_k));
            ldsm4(b1[nxt][0], b1[nxt][1], b1[nxt][2], b1[nxt][3],
                  bb + swz(warpCol + 16 + b_n, k0 + b_k));
        }
        mma16816(c[0], a[cur], b0[cur][0], b0[cur][1]);
        mma16816(c[1], a[cur], b0[cur][2], b0[cur][3]);
        mma16816(c[2], a[cur], b1[cur][0], b1[cur][1]);
        mma16816(c[3], a[cur], b1[cur][2], b1[cur][3]);
    }

    const int crow = lane >> 2;
    const int ccol = (lane & 3) * 2;
#pragma unroll
    for (int ni = 0; ni < 4; ni++) {
        int colg = warpCol + ni * 8 + ccol;
        float bx = 0.f, by = 0.f;
        if (doBias) { bx = bias[colg]; by = bias[colg + 1]; }
        int r0 = rbase + warpRow + crow;
        int r1 = r0 + 8;
        if (r0 < M) {
            float2 v = make_float2(c[ni][0] + bx, c[ni][1] + by);
            *reinterpret_cast<float2*>(C + (size_t)r0 * FDIM + colg) = v;
        }
        if (r1 < M) {
            float2 v = make_float2(c[ni][2] + bx, c[ni][3] + by);
            *reinterpret_cast<float2*>(C + (size_t)r1 * FDIM + colg) = v;
        }
    }
}

// ---------------- CSR aggregate: one warp per node, unrolled x4 ----------------

__global__ void __launch_bounds__(256) k_aggregate(
    const int* __restrict__ rowptr, const int* __restrict__ srow,
    const float* __restrict__ snorm, const float* __restrict__ dinv,
    const float* __restrict__ bias, const float* __restrict__ t,
    float* __restrict__ h, int n)
{
    int node = blockIdx.x * 8 + (threadIdx.x >> 5);
    if (node >= n) return;
    const int lane = threadIdx.x & 31;
    const int f4 = lane * 4;

    float d = __ldg(dinv + node);
    float d2 = d * d;
    float4 tv = *reinterpret_cast<const float4*>(t + (size_t)node * FDIM + f4);
    float4 bv = *reinterpret_cast<const float4*>(bias + f4);
    float4 acc;
    acc.x = fmaf(tv.x, d2, bv.x);
    acc.y = fmaf(tv.y, d2, bv.y);
    acc.z = fmaf(tv.z, d2, bv.z);
    acc.w = fmaf(tv.w, d2, bv.w);

    int j = __ldg(rowptr + node);
    const int jend = __ldg(rowptr + node + 1);

    for (; j + 3 < jend; j += 4) {
        int r0 = __ldg(srow + j);
        int r1 = __ldg(srow + j + 1);
        int r2 = __ldg(srow + j + 2);
        int r3 = __ldg(srow + j + 3);
        float w0 = __ldg(snorm + j);
        float w1 = __ldg(snorm + j + 1);
        float w2 = __ldg(snorm + j + 2);
        float w3 = __ldg(snorm + j + 3);
        float4 v0 = *reinterpret_cast<const float4*>(t + (size_t)r0 * FDIM + f4);
        float4 v1 = *reinterpret_cast<const float4*>(t + (size_t)r1 * FDIM + f4);
        float4 v2 = *reinterpret_cast<const float4*>(t + (size_t)r2 * FDIM + f4);
        float4 v3 = *reinterpret_cast<const float4*>(t + (size_t)r3 * FDIM + f4);
        acc.x = fmaf(v0.x, w0, acc.x); acc.y = fmaf(v0.y, w0, acc.y);
        acc.z = fmaf(v0.z, w0, acc.z); acc.w = fmaf(v0.w, w0, acc.w);
        acc.x = fmaf(v1.x, w1, acc.x); acc.y = fmaf(v1.y, w1, acc.y);
        acc.z = fmaf(v1.z, w1, acc.z); acc.w = fmaf(v1.w, w1, acc.w);
        acc.x = fmaf(v2.x, w2, acc.x); acc.y = fmaf(v2.y, w2, acc.y);
        acc.z = fmaf(v2.z, w2, acc.z); acc.w = fmaf(v2.w, w2, acc.w);
        acc.x = fmaf(v3.x, w3, acc.x); acc.y = fmaf(v3.y, w3, acc.y);
        acc.z = fmaf(v3.z, w3, acc.z); acc.w = fmaf(v3.w, w3, acc.w);
    }
    for (; j < jend; j++) {
        int r0 = __ldg(srow + j);
        float w0 = __ldg(snorm + j);
        float4 v0 = *reinterpret_cast<const float4*>(t + (size_t)r0 * FDIM + f4);
        acc.x = fmaf(v0.x, w0, acc.x); acc.y = fmaf(v0.y, w0, acc.y);
        acc.z = fmaf(v0.z, w0, acc.z); acc.w = fmaf(v0.w, w0, acc.w);
    }

    *reinterpret_cast<float4*>(h + (size_t)node * FDIM + f4) = acc;
}

// ---------------- launch ----------------

extern "C" void kernel_launch(void* const* d_in, const int* in_sizes, int n_in,
                              void* d_out, int out_size) {
    const float* x    = (const float*)d_in[0];
    const int*   ei   = (const int*)  d_in[1];
    const float* ew   = (const float*)d_in[2];
    const float* Wc[4] = {(const float*)d_in[3], (const float*)d_in[5],
                          (const float*)d_in[7], (const float*)d_in[9]};
    const float* bc[4] = {(const float*)d_in[4], (const float*)d_in[6],
                          (const float*)d_in[8], (const float*)d_in[10]};
    const float* Wout = (const float*)d_in[11];
    const float* bout = (const float*)d_in[12];
    float* out = (float*)d_out;

    const int N = in_sizes[0] / FDIM;
    const int E = in_sizes[2];
    const int* rowp = ei;
    const int* colp = ei + E;

    float *t, *h, *deg, *dinv, *snorm;
    int *cnt, *rowptr, *cur, *srow, *bsum, *boffs;
    __nv_bfloat16 *whi, *wlo;
    cudaGetSymbolAddress((void**)&t, g_t);
    cudaGetSymbolAddress((void**)&h, g_h);
    cudaGetSymbolAddress((void**)&deg, g_deg);
    cudaGetSymbolAddress((void**)&dinv, g_dinv);
    cudaGetSymbolAddress((void**)&cnt, g_cnt);
    cudaGetSymbolAddress((void**)&rowptr, g_rowptr);
    cudaGetSymbolAddress((void**)&cur, g_cursor);
    cudaGetSymbolAddress((void**)&srow, g_srow);
    cudaGetSymbolAddress((void**)&snorm, g_snorm);
    cudaGetSymbolAddress((void**)&bsum, g_bsum);
    cudaGetSymbolAddress((void**)&boffs, g_boffs);
    cudaGetSymbolAddress((void**)&whi, g_whi);
    cudaGetSymbolAddress((void**)&wlo, g_wlo);

    static const int SMEM_DYN = 98304;
    cudaFuncSetAttribute(k_gemm_mma, cudaFuncAttributeMaxDynamicSharedMemorySize, SMEM_DYN);

    const int TB = 256;
    const int nScanBlk = (N + SCAN_B - 1) / SCAN_B;
    const int wpBlocks = (16384 + TB - 1) / TB;
    const int gemmBlocks = (N + BM - 1) / BM;
    const int aggBlocks  = (N + 7) / 8;

    // Launch order: k_gemm_mma is launch #4 (ncu captures my 4th launch).
    k_wprep<<<wpBlocks, TB>>>(Wc[0], whi, wlo);                                // 1
    k_init<<<(N + TB - 1) / TB, TB>>>(deg, cnt, cur, N);                       // 2
    k_deg_hist<<<(E + TB - 1) / TB, TB>>>(colp, ew, deg, cnt, E);              // 3
    k_gemm_mma<<<gemmBlocks, GT, SMEM_DYN>>>(x, whi, wlo, nullptr, t, N, 0, 0);// 4 <- profiled
    k_dinv<<<(N + TB - 1) / TB, TB>>>(deg, dinv, N);                           // 5
    k_scan_local<<<nScanBlk, SCAN_B>>>(cnt, rowptr, bsum, N);                  // 6
    k_scan_mid<<<1, MAXBLK>>>(bsum, boffs, nScanBlk);                          // 7
    k_scan_add<<<nScanBlk, SCAN_B>>>(rowptr, boffs, N, E);                     // 8
    k_fill<<<(E + TB - 1) / TB, TB>>>(rowp, colp, ew, dinv, rowptr, cur, srow, snorm, E);
    for (int l = 1; l < 4; l++)
        k_wprep<<<wpBlocks, TB>>>(Wc[l], whi + l * 16384, wlo + l * 16384);
    k_wprep<<<wpBlocks, TB>>>(Wout, whi + 4 * 16384, wlo + 4 * 16384);

    k_aggregate<<<aggBlocks, TB>>>(rowptr, srow, snorm, dinv, bc[0], t, h, N);

    for (int l = 1; l < 4; l++) {
        k_gemm_mma<<<gemmBlocks, GT, SMEM_DYN>>>(h, whi + l * 16384, wlo + l * 16384,
                                                 nullptr, t, N, 1, 0);
        k_aggregate<<<aggBlocks, TB>>>(rowptr, srow, snorm, dinv, bc[l], t, h, N);
    }

    k_gemm_mma<<<gemmBlocks, GT, SMEM_DYN>>>(h, whi + 4 * 16384, wlo + 4 * 16384,
                                             bout, out, N, 0, 1);
}

// round 9
// speedup vs baseline: 1.3667x; 1.3667x over previous
#include <cuda_runtime.h>
#include <cuda_bf16.h>
#include <cstdint>

// ---------------------------------------------------------------------------
// GCN: 4x GCNConv(128->128) + output linear(128->128), N=100000, E=1600000.
// Round 9: revert to 256-thr 2x4 GEMM (r8 occupancy push regressed); fuse the
// 3 split terms per k-step to share fragments: 8 ldsm -> 24 mma (was 12->24).
// ---------------------------------------------------------------------------

#define NMAX 100096
#define EMAX 1600000
#define FDIM 128
#define SCAN_B 1024
#define MAXBLK 128
#define BM 64

__device__ float g_t[(size_t)NMAX * FDIM];
__device__ float g_h[(size_t)NMAX * FDIM];
__device__ float g_deg[NMAX];
__device__ float g_dinv[NMAX];
__device__ int   g_cnt[NMAX];
__device__ int   g_rowptr[NMAX + 1];
__device__ int   g_cursor[NMAX];
__device__ int   g_srow[EMAX];
__device__ float g_snorm[EMAX];
__device__ int   g_bsum[MAXBLK];
__device__ int   g_boffs[MAXBLK];
__device__ __align__(16) __nv_bfloat16 g_whi[5 * 16384];
__device__ __align__(16) __nv_bfloat16 g_wlo[5 * 16384];

// ---------------- helpers ----------------

__device__ __forceinline__ uint32_t smem_u32(const void* p) {
    uint32_t a;
    asm("{ .reg .u64 t; cvta.to.shared.u64 t, %1; cvt.u32.u64 %0, t; }" : "=r"(a) : "l"(p));
    return a;
}

__device__ __forceinline__ void ldsm4(uint32_t& r0, uint32_t& r1, uint32_t& r2,
                                      uint32_t& r3, uint32_t addr) {
    asm volatile("ldmatrix.sync.aligned.m8n8.x4.shared.b16 {%0,%1,%2,%3}, [%4];"
                 : "=r"(r0), "=r"(r1), "=r"(r2), "=r"(r3) : "r"(addr));
}

__device__ __forceinline__ void mma16816(float* c, const uint32_t* a,
                                         uint32_t b0, uint32_t b1) {
    asm volatile(
        "mma.sync.aligned.m16n8k16.row.col.f32.bf16.bf16.f32 "
        "{%0,%1,%2,%3}, {%4,%5,%6,%7}, {%8,%9}, {%0,%1,%2,%3};"
        : "+f"(c[0]), "+f"(c[1]), "+f"(c[2]), "+f"(c[3])
        : "r"(a[0]), "r"(a[1]), "r"(a[2]), "r"(a[3]), "r"(b0), "r"(b1));
}

__device__ __forceinline__ void cp16(uint32_t dst, const void* src) {
    asm volatile("cp.async.ca.shared.global [%0], [%1], 16;" :: "r"(dst), "l"(src));
}

// XOR-swizzled: 256B rows (128 bf16); addr(r,k) = r*256 + ((k>>3)^(r&7))*16 + (k&7)*2
__device__ __forceinline__ uint32_t swz(int r, int k) {
    return (uint32_t)((r << 8) + ((((k >> 3) ^ (r & 7)) << 4)) + ((k & 7) << 1));
}

// ---------------- degree + histogram ----------------

__global__ void k_init(float* __restrict__ deg, int* __restrict__ cnt,
                       int* __restrict__ cur, int n) {
    int i = blockIdx.x * blockDim.x + threadIdx.x;
    if (i < n) { deg[i] = 1.0f; cnt[i] = 0; cur[i] = 0; }
}

__global__ void k_deg_hist(const int* __restrict__ col, const float* __restrict__ ew,
                           float* __restrict__ deg, int* __restrict__ cnt, int E) {
    int e = blockIdx.x * blockDim.x + threadIdx.x;
    if (e < E) {
        int c = col[e];
        atomicAdd(&deg[c], ew[e]);
        atomicAdd(&cnt[c], 1);
    }
}

__global__ void k_dinv(const float* __restrict__ deg, float* __restrict__ dinv, int n) {
    int i = blockIdx.x * blockDim.x + threadIdx.x;
    if (i < n) {
        float d = deg[i];
        dinv[i] = (d > 0.0f) ? rsqrtf(d) : 0.0f;
    }
}

// ---------------- 3-phase scan ----------------

__global__ void __launch_bounds__(SCAN_B) k_scan_local(
    const int* __restrict__ cnt, int* __restrict__ rowptr,
    int* __restrict__ bsum, int n)
{
    __shared__ int s[SCAN_B];
    const int tid = threadIdx.x;
    const int i = blockIdx.x * SCAN_B + tid;
    int v = (i < n) ? cnt[i] : 0;
    s[tid] = v;
    __syncthreads();
#pragma unroll
    for (int ofs = 1; ofs < SCAN_B; ofs <<= 1) {
        int t = (tid >= ofs) ? s[tid - ofs] : 0;
        __syncthreads();
        s[tid] += t;
        __syncthreads();
    }
    if (i < n) rowptr[i] = s[tid] - v;
    if (tid == SCAN_B - 1) bsum[blockIdx.x] = s[tid];
}

__global__ void __launch_bounds__(MAXBLK) k_scan_mid(
    const int* __restrict__ bsum, int* __restrict__ boffs, int nb)
{
    __shared__ int s[MAXBLK];
    const int tid = threadIdx.x;
    int v = (tid < nb) ? bsum[tid] : 0;
    s[tid] = v;
    __syncthreads();
#pragma unroll
    for (int ofs = 1; ofs < MAXBLK; ofs <<= 1) {
        int t = (tid >= ofs) ? s[tid - ofs] : 0;
        __syncthreads();
        s[tid] += t;
        __syncthreads();
    }
    if (tid < nb) boffs[tid] = s[tid] - v;
}

__global__ void __launch_bounds__(SCAN_B) k_scan_add(
    int* __restrict__ rowptr, const int* __restrict__ boffs, int n, int E)
{
    const int i = blockIdx.x * SCAN_B + threadIdx.x;
    if (i < n) rowptr[i] += boffs[blockIdx.x];
    if (i == 0) rowptr[n] = E;
}

// ---------------- counting-sort fill ----------------

__global__ void k_fill(const int* __restrict__ row, const int* __restrict__ col,
                       const float* __restrict__ ew, const float* __restrict__ dinv,
                       const int* __restrict__ rowptr, int* __restrict__ cur,
                       int* __restrict__ srow, float* __restrict__ snorm, int E) {
    int e = blockIdx.x * blockDim.x + threadIdx.x;
    if (e >= E) return;
    int r = row[e];
    int c = col[e];
    int pos = rowptr[c] + atomicAdd(&cur[c], 1);
    srow[pos] = r;
    snorm[pos] = dinv[r] * ew[e] * dinv[c];
}

// ---------------- weight prep ----------------

__global__ void k_wprep(const float* __restrict__ W, __nv_bfloat16* __restrict__ dhi,
                        __nv_bfloat16* __restrict__ dlo) {
    int idx = blockIdx.x * blockDim.x + threadIdx.x;
    if (idx >= 16384) return;
    int n = idx >> 7, k = idx & 127;
    float w = W[k * 128 + n];                 // B[n][k] = W[k][n]
    __nv_bfloat16 hi = __float2bfloat16(w);
    __nv_bfloat16 lo = __float2bfloat16(w - __bfloat162float(hi));
    dhi[n * 128 + k] = hi;
    dlo[n * 128 + k] = lo;
}

// ---------------- HMMA GEMM: C[M,128] = act(A[M,128]) @ W (+bias) ----------------
// BM=64, 256 threads, 8 warps 2x4 (32x32 per warp), term-fused mainloop:
// per k-step load {Ahi,Alo,Bhi,Blo} frags once, issue all 3 split-term MMAs.

__global__ void __launch_bounds__(256, 2) k_gemm_mma(
    const float* __restrict__ A, const __nv_bfloat16* __restrict__ whi,
    const __nv_bfloat16* __restrict__ wlo, const float* __restrict__ bias,
    float* __restrict__ C, int M, int doRelu, int doBias)
{
    extern __shared__ char sm[];
    char* sAhi = sm;
    char* sAlo = sm + 16384;
    char* sWhi = sm + 32768;
    char* sWlo = sm + 65536;

    const int tid = threadIdx.x;
    const int wid = tid >> 5;
    const int lane = tid & 31;
    const int rbase = blockIdx.x * BM;

    const uint32_t uWhi = smem_u32(sWhi);
    const uint32_t uWlo = smem_u32(sWlo);
    const uint32_t uAhi = smem_u32(sAhi);
    const uint32_t uAlo = smem_u32(sAlo);

    for (int i = tid; i < 2048; i += 256) {
        int r = i >> 4, c = i & 15;
        uint32_t doff = (uint32_t)((r << 8) + ((c ^ (r & 7)) << 4));
        cp16(uWhi + doff, whi + r * 128 + c * 8);
        cp16(uWlo + doff, wlo + r * 128 + c * 8);
    }
    asm volatile("cp.async.commit_group;" ::: "memory");

    for (int idx = tid; idx < BM * 32; idx += 256) {
        int row = idx >> 5;
        int c4 = (idx & 31) << 2;
        int grow = rbase + row;
        float4 av = make_float4(0.f, 0.f, 0.f, 0.f);
        if (grow < M)
            av = *reinterpret_cast<const float4*>(A + (size_t)grow * FDIM + c4);
        if (doRelu) {
            av.x = fmaxf(av.x, 0.f); av.y = fmaxf(av.y, 0.f);
            av.z = fmaxf(av.z, 0.f); av.w = fmaxf(av.w, 0.f);
        }
        __nv_bfloat162 h01, h23, l01, l23;
        h01.x = __float2bfloat16(av.x);
        h01.y = __float2bfloat16(av.y);
        h23.x = __float2bfloat16(av.z);
        h23.y = __float2bfloat16(av.w);
        l01.x = __float2bfloat16(av.x - __bfloat162float(h01.x));
        l01.y = __float2bfloat16(av.y - __bfloat162float(h01.y));
        l23.x = __float2bfloat16(av.z - __bfloat162float(h23.x));
        l23.y = __float2bfloat16(av.w - __bfloat162float(h23.y));
        uint32_t off = swz(row, c4);
        *reinterpret_cast<uint32_t*>(sAhi + off)     = *reinterpret_cast<uint32_t*>(&h01);
        *reinterpret_cast<uint32_t*>(sAhi + off + 4) = *reinterpret_cast<uint32_t*>(&h23);
        *reinterpret_cast<uint32_t*>(sAlo + off)     = *reinterpret_cast<uint32_t*>(&l01);
        *reinterpret_cast<uint32_t*>(sAlo + off + 4) = *reinterpret_cast<uint32_t*>(&l23);
    }
    asm volatile("cp.async.wait_group 0;" ::: "memory");
    __syncthreads();

    const int warpRow = (wid & 1) * 32;
    const int warpCol = (wid >> 1) * 32;
    const int a_r = lane & 15;
    const int a_k = (lane >> 4) << 3;
    const int b_n = (lane & 7) + ((lane >> 4) << 3);
    const int b_k = ((lane >> 3) & 1) << 3;

    float c[2][4][4];
#pragma unroll
    for (int mi = 0; mi < 2; mi++)
#pragma unroll
        for (int ni = 0; ni < 4; ni++)
#pragma unroll
            for (int q = 0; q < 4; q++) c[mi][ni][q] = 0.0f;

    // double-buffered fragments for all 4 operand families
    uint32_t ah0[2][4], ah1[2][4], al0[2][4], al1[2][4];
    uint32_t bh0[2][4], bh1[2][4], bl0[2][4], bl1[2][4];

#define LOADK(buf, k0)                                                          \
    do {                                                                        \
        ldsm4(ah0[buf][0], ah0[buf][1], ah0[buf][2], ah0[buf][3],               \
              uAhi + swz(warpRow + a_r,      (k0) + a_k));                      \
        ldsm4(ah1[buf][0], ah1[buf][1], ah1[buf][2], ah1[buf][3],               \
              uAhi + swz(warpRow + 16 + a_r, (k0) + a_k));                      \
        ldsm4(al0[buf][0], al0[buf][1], al0[buf][2], al0[buf][3],               \
              uAlo + swz(warpRow + a_r,      (k0) + a_k));                      \
        ldsm4(al1[buf][0], al1[buf][1], al1[buf][2], al1[buf][3],               \
              uAlo + swz(warpRow + 16 + a_r, (k0) + a_k));                      \
        ldsm4(bh0[buf][0], bh0[buf][1], bh0[buf][2], bh0[buf][3],               \
              uWhi + swz(warpCol + b_n,      (k0) + b_k));                      \
        ldsm4(bh1[buf][0], bh1[buf][1], bh1[buf][2], bh1[buf][3],               \
              uWhi + swz(warpCol + 16 + b_n, (k0) + b_k));                      \
        ldsm4(bl0[buf][0], bl0[buf][1], bl0[buf][2], bl0[buf][3],               \
              uWlo + swz(warpCol + b_n,      (k0) + b_k));                      \
        ldsm4(bl1[buf][0], bl1[buf][1], bl1[buf][2], bl1[buf][3],               \
              uWlo + swz(warpCol + 16 + b_n, (k0) + b_k));                      \
    } while (0)

    LOADK(0, 0);
#pragma unroll
    for (int it = 0; it < 8; it++) {
        const int cur = it & 1, nxt = cur ^ 1;
        if (it < 7) LOADK(nxt, (it + 1) << 4);
        // term0: Ahi * Whi
        mma16816(c[0][0], ah0[cur], bh0[cur][0], bh0[cur][1]);
        mma16816(c[0][1], ah0[cur], bh0[cur][2], bh0[cur][3]);
        mma16816(c[0][2], ah0[cur], bh1[cur][0], bh1[cur][1]);
        mma16816(c[0][3], ah0[cur], bh1[cur][2], bh1[cur][3]);
        mma16816(c[1][0], ah1[cur], bh0[cur][0], bh0[cur][1]);
        mma16816(c[1][1], ah1[cur], bh0[cur][2], bh0[cur][3]);
        mma16816(c[1][2], ah1[cur], bh1[cur][0], bh1[cur][1]);
        mma16816(c[1][3], ah1[cur], bh1[cur][2], bh1[cur][3]);
        // term1: Alo * Whi
        mma16816(c[0][0], al0[cur], bh0[cur][0], bh0[cur][1]);
        mma16816(c[0][1], al0[cur], bh0[cur][2], bh0[cur][3]);
        mma16816(c[0][2], al0[cur], bh1[cur][0], bh1[cur][1]);
        mma16816(c[0][3], al0[cur], bh1[cur][2], bh1[cur][3]);
        mma16816(c[1][0], al1[cur], bh0[cur][0], bh0[cur][1]);
        mma16816(c[1][1], al1[cur], bh0[cur][2], bh0[cur][3]);
        mma16816(c[1][2], al1[cur], bh1[cur][0], bh1[cur][1]);
        mma16816(c[1][3], al1[cur], bh1[cur][2], bh1[cur][3]);
        // term2: Ahi * Wlo
        mma16816(c[0][0], ah0[cur], bl0[cur][0], bl0[cur][1]);
        mma16816(c[0][1], ah0[cur], bl0[cur][2], bl0[cur][3]);
        mma16816(c[0][2], ah0[cur], bl1[cur][0], bl1[cur][1]);
        mma16816(c[0][3], ah0[cur], bl1[cur][2], bl1[cur][3]);
        mma16816(c[1][0], ah1[cur], bl0[cur][0], bl0[cur][1]);
        mma16816(c[1][1], ah1[cur], bl0[cur][2], bl0[cur][3]);
        mma16816(c[1][2], ah1[cur], bl1[cur][0], bl1[cur][1]);
        mma16816(c[1][3], ah1[cur], bl1[cur][2], bl1[cur][3]);
    }
#undef LOADK

    const int crow = lane >> 2;
    const int ccol = (lane & 3) * 2;
#pragma unroll
    for (int mi = 0; mi < 2; mi++) {
#pragma unroll
        for (int ni = 0; ni < 4; ni++) {
            int colg = warpCol + ni * 8 + ccol;
            float bx = 0.f, by = 0.f;
            if (doBias) { bx = bias[colg]; by = bias[colg + 1]; }
            int r0 = rbase + warpRow + mi * 16 + crow;
            int r1 = r0 + 8;
            if (r0 < M) {
                float2 v = make_float2(c[mi][ni][0] + bx, c[mi][ni][1] + by);
                *reinterpret_cast<float2*>(C + (size_t)r0 * FDIM + colg) = v;
            }
            if (r1 < M) {
                float2 v = make_float2(c[mi][ni][2] + bx, c[mi][ni][3] + by);
                *reinterpret_cast<float2*>(C + (size_t)r1 * FDIM + colg) = v;
            }
        }
    }
}

// ---------------- CSR aggregate: one warp per node, unrolled x4 ----------------

__global__ void __launch_bounds__(256) k_aggregate(
    const int* __restrict__ rowptr, const int* __restrict__ srow,
    const float* __restrict__ snorm, const float* __restrict__ dinv,
    const float* __restrict__ bias, const float* __restrict__ t,
    float* __restrict__ h, int n)
{
    int node = blockIdx.x * 8 + (threadIdx.x >> 5);
    if (node >= n) return;
    const int lane = threadIdx.x & 31;
    const int f4 = lane * 4;

    float d = __ldg(dinv + node);
    float d2 = d * d;
    float4 tv = *reinterpret_cast<const float4*>(t + (size_t)node * FDIM + f4);
    float4 bv = *reinterpret_cast<const float4*>(bias + f4);
    float4 acc;
    acc.x = fmaf(tv.x, d2, bv.x);
    acc.y = fmaf(tv.y, d2, bv.y);
    acc.z = fmaf(tv.z, d2, bv.z);
    acc.w = fmaf(tv.w, d2, bv.w);

    int j = __ldg(rowptr + node);
    const int jend = __ldg(rowptr + node + 1);

    for (; j + 3 < jend; j += 4) {
        int r0 = __ldg(srow + j);
        int r1 = __ldg(srow + j + 1);
        int r2 = __ldg(srow + j + 2);
        int r3 = __ldg(srow + j + 3);
        float w0 = __ldg(snorm + j);
        float w1 = __ldg(snorm + j + 1);
        float w2 = __ldg(snorm + j + 2);
        float w3 = __ldg(snorm + j + 3);
        float4 v0 = *reinterpret_cast<const float4*>(t + (size_t)r0 * FDIM + f4);
        float4 v1 = *reinterpret_cast<const float4*>(t + (size_t)r1 * FDIM + f4);
        float4 v2 = *reinterpret_cast<const float4*>(t + (size_t)r2 * FDIM + f4);
        float4 v3 = *reinterpret_cast<const float4*>(t + (size_t)r3 * FDIM + f4);
        acc.x = fmaf(v0.x, w0, acc.x); acc.y = fmaf(v0.y, w0, acc.y);
        acc.z = fmaf(v0.z, w0, acc.z); acc.w = fmaf(v0.w, w0, acc.w);
        acc.x = fmaf(v1.x, w1, acc.x); acc.y = fmaf(v1.y, w1, acc.y);
        acc.z = fmaf(v1.z, w1, acc.z); acc.w = fmaf(v1.w, w1, acc.w);
        acc.x = fmaf(v2.x, w2, acc.x); acc.y = fmaf(v2.y, w2, acc.y);
        acc.z = fmaf(v2.z, w2, acc.z); acc.w = fmaf(v2.w, w2, acc.w);
        acc.x = fmaf(v3.x, w3, acc.x); acc.y = fmaf(v3.y, w3, acc.y);
        acc.z = fmaf(v3.z, w3, acc.z); acc.w = fmaf(v3.w, w3, acc.w);
    }
    for (; j < jend; j++) {
        int r0 = __ldg(srow + j);
        float w0 = __ldg(snorm + j);
        float4 v0 = *reinterpret_cast<const float4*>(t + (size_t)r0 * FDIM + f4);
        acc.x = fmaf(v0.x, w0, acc.x); acc.y = fmaf(v0.y, w0, acc.y);
        acc.z = fmaf(v0.z, w0, acc.z); acc.w = fmaf(v0.w, w0, acc.w);
    }

    *reinterpret_cast<float4*>(h + (size_t)node * FDIM + f4) = acc;
}

// ---------------- launch ----------------

extern "C" void kernel_launch(void* const* d_in, const int* in_sizes, int n_in,
                              void* d_out, int out_size) {
    const float* x    = (const float*)d_in[0];
    const int*   ei   = (const int*)  d_in[1];
    const float* ew   = (const float*)d_in[2];
    const float* Wc[4] = {(const float*)d_in[3], (const float*)d_in[5],
                          (const float*)d_in[7], (const float*)d_in[9]};
    const float* bc[4] = {(const float*)d_in[4], (const float*)d_in[6],
                          (const float*)d_in[8], (const float*)d_in[10]};
    const float* Wout = (const float*)d_in[11];
    const float* bout = (const float*)d_in[12];
    float* out = (float*)d_out;

    const int N = in_sizes[0] / FDIM;
    const int E = in_sizes[2];
    const int* rowp = ei;
    const int* colp = ei + E;

    float *t, *h, *deg, *dinv, *snorm;
    int *cnt, *rowptr, *cur, *srow, *bsum, *boffs;
    __nv_bfloat16 *whi, *wlo;
    cudaGetSymbolAddress((void**)&t, g_t);
    cudaGetSymbolAddress((void**)&h, g_h);
    cudaGetSymbolAddress((void**)&deg, g_deg);
    cudaGetSymbolAddress((void**)&dinv, g_dinv);
    cudaGetSymbolAddress((void**)&cnt, g_cnt);
    cudaGetSymbolAddress((void**)&rowptr, g_rowptr);
    cudaGetSymbolAddress((void**)&cur, g_cursor);
    cudaGetSymbolAddress((void**)&srow, g_srow);
    cudaGetSymbolAddress((void**)&snorm, g_snorm);
    cudaGetSymbolAddress((void**)&bsum, g_bsum);
    cudaGetSymbolAddress((void**)&boffs, g_boffs);
    cudaGetSymbolAddress((void**)&whi, g_whi);
    cudaGetSymbolAddress((void**)&wlo, g_wlo);

    static const int SMEM_DYN = 98304;
    cudaFuncSetAttribute(k_gemm_mma, cudaFuncAttributeMaxDynamicSharedMemorySize, SMEM_DYN);

    const int TB = 256;
    const int nScanBlk = (N + SCAN_B - 1) / SCAN_B;
    const int wpBlocks = (16384 + TB - 1) / TB;
    const int gemmBlocks = (N + BM - 1) / BM;
    const int aggBlocks  = (N + 7) / 8;

    // Launch order: k_gemm_mma is launch #4 (ncu captures my 4th launch).
    k_wprep<<<wpBlocks, TB>>>(Wc[0], whi, wlo);                                // 1
    k_init<<<(N + TB - 1) / TB, TB>>>(deg, cnt, cur, N);                       // 2
    k_deg_hist<<<(E + TB - 1) / TB, TB>>>(colp, ew, deg, cnt, E);              // 3
    k_gemm_mma<<<gemmBlocks, TB, SMEM_DYN>>>(x, whi, wlo, nullptr, t, N, 0, 0);// 4 <- profiled
    k_dinv<<<(N + TB - 1) / TB, TB>>>(deg, dinv, N);                           // 5
    k_scan_local<<<nScanBlk, SCAN_B>>>(cnt, rowptr, bsum, N);                  // 6
    k_scan_mid<<<1, MAXBLK>>>(bsum, boffs, nScanBlk);                          // 7
    k_scan_add<<<nScanBlk, SCAN_B>>>(rowptr, boffs, N, E);                     // 8
    k_fill<<<(E + TB - 1) / TB, TB>>>(rowp, colp, ew, dinv, rowptr, cur, srow, snorm, E);
    for (int l = 1; l < 4; l++)
        k_wprep<<<wpBlocks, TB>>>(Wc[l], whi + l * 16384, wlo + l * 16384);
    k_wprep<<<wpBlocks, TB>>>(Wout, whi + 4 * 16384, wlo + 4 * 16384);

    k_aggregate<<<aggBlocks, TB>>>(rowptr, srow, snorm, dinv, bc[0], t, h, N);

    for (int l = 1; l < 4; l++) {
        k_gemm_mma<<<gemmBlocks, TB, SMEM_DYN>>>(h, whi + l * 16384, wlo + l * 16384,
                                                 nullptr, t, N, 1, 0);
        k_aggregate<<<aggBlocks, TB>>>(rowptr, srow, snorm, dinv, bc[l], t, h, N);
    }

    k_gemm_mma<<<gemmBlocks, TB, SMEM_DYN>>>(h, whi + 4 * 16384, wlo + 4 * 16384,
                                             bout, out, N, 0, 1);
}

// round 10
// speedup vs baseline: 1.6474x; 1.2054x over previous
#include <cuda_runtime.h>
#include <cuda_bf16.h>
#include <cstdint>

// ---------------------------------------------------------------------------
// GCN: 4x GCNConv(128->128) + output linear(128->128), N=100000, E=1600000.
// Round 10: producers (aggregate / xprep) write activations pre-split as
// bf16 hi/lo; GEMM stages A via pure cp.async (no convert phase).
// ---------------------------------------------------------------------------

#define NMAX 100096
#define EMAX 1600000
#define FDIM 128
#define SCAN_B 1024
#define MAXBLK 128
#define BM 64

__device__ float g_t[(size_t)NMAX * FDIM];                      // GEMM out (fp32)
__device__ __align__(16) __nv_bfloat16 g_hhi[(size_t)NMAX * FDIM];
__device__ __align__(16) __nv_bfloat16 g_hlo[(size_t)NMAX * FDIM];
__device__ __align__(16) __nv_bfloat16 g_xhi[(size_t)NMAX * FDIM];
__device__ __align__(16) __nv_bfloat16 g_xlo[(size_t)NMAX * FDIM];
__device__ float g_deg[NMAX];
__device__ float g_dinv[NMAX];
__device__ int   g_cnt[NMAX];
__device__ int   g_rowptr[NMAX + 1];
__device__ int   g_cursor[NMAX];
__device__ int   g_srow[EMAX];
__device__ float g_snorm[EMAX];
__device__ int   g_bsum[MAXBLK];
__device__ int   g_boffs[MAXBLK];
__device__ __align__(16) __nv_bfloat16 g_whi[5 * 16384];
__device__ __align__(16) __nv_bfloat16 g_wlo[5 * 16384];

// ---------------- helpers ----------------

__device__ __forceinline__ uint32_t smem_u32(const void* p) {
    uint32_t a;
    asm("{ .reg .u64 t; cvta.to.shared.u64 t, %1; cvt.u32.u64 %0, t; }" : "=r"(a) : "l"(p));
    return a;
}

__device__ __forceinline__ void ldsm4(uint32_t& r0, uint32_t& r1, uint32_t& r2,
                                      uint32_t& r3, uint32_t addr) {
    asm volatile("ldmatrix.sync.aligned.m8n8.x4.shared.b16 {%0,%1,%2,%3}, [%4];"
                 : "=r"(r0), "=r"(r1), "=r"(r2), "=r"(r3) : "r"(addr));
}

__device__ __forceinline__ void mma16816(float* c, const uint32_t* a,
                                         uint32_t b0, uint32_t b1) {
    asm volatile(
        "mma.sync.aligned.m16n8k16.row.col.f32.bf16.bf16.f32 "
        "{%0,%1,%2,%3}, {%4,%5,%6,%7}, {%8,%9}, {%0,%1,%2,%3};"
        : "+f"(c[0]), "+f"(c[1]), "+f"(c[2]), "+f"(c[3])
        : "r"(a[0]), "r"(a[1]), "r"(a[2]), "r"(a[3]), "r"(b0), "r"(b1));
}

__device__ __forceinline__ void cp16(uint32_t dst, const void* src) {
    asm volatile("cp.async.ca.shared.global [%0], [%1], 16;" :: "r"(dst), "l"(src));
}

// XOR-swizzled: 256B rows (128 bf16); addr(r,k) = r*256 + ((k>>3)^(r&7))*16 + (k&7)*2
__device__ __forceinline__ uint32_t swz(int r, int k) {
    return (uint32_t)((r << 8) + ((((k >> 3) ^ (r & 7)) << 4)) + ((k & 7) << 1));
}

// pack 2 floats -> bf16x2 (uint32)
__device__ __forceinline__ uint32_t bfpack(float a, float b) {
    __nv_bfloat162 v;
    v.x = __float2bfloat16(a);
    v.y = __float2bfloat16(b);
    return *reinterpret_cast<uint32_t*>(&v);
}
__device__ __forceinline__ float bflo(uint32_t p) {
    __nv_bfloat162 v = *reinterpret_cast<__nv_bfloat162*>(&p);
    return __bfloat162float(v.x);
}
__device__ __forceinline__ float bfhi(uint32_t p) {
    __nv_bfloat162 v = *reinterpret_cast<__nv_bfloat162*>(&p);
    return __bfloat162float(v.y);
}

// ---------------- x prep: fp32 -> hi/lo bf16 (no relu) ----------------

__global__ void k_xprep(const float* __restrict__ x, __nv_bfloat16* __restrict__ xhi,
                        __nv_bfloat16* __restrict__ xlo, int total4) {
    int i = blockIdx.x * blockDim.x + threadIdx.x;
    if (i >= total4) return;
    float4 v = reinterpret_cast<const float4*>(x)[i];
    uint32_t h01 = bfpack(v.x, v.y);
    uint32_t h23 = bfpack(v.z, v.w);
    uint32_t l01 = bfpack(v.x - bflo(h01), v.y - bfhi(h01));
    uint32_t l23 = bfpack(v.z - bflo(h23), v.w - bfhi(h23));
    reinterpret_cast<uint2*>(xhi)[i] = make_uint2(h01, h23);
    reinterpret_cast<uint2*>(xlo)[i] = make_uint2(l01, l23);
}

// ---------------- degree + histogram ----------------

__global__ void k_init(float* __restrict__ deg, int* __restrict__ cnt,
                       int* __restrict__ cur, int n) {
    int i = blockIdx.x * blockDim.x + threadIdx.x;
    if (i < n) { deg[i] = 1.0f; cnt[i] = 0; cur[i] = 0; }
}

__global__ void k_deg_hist(const int* __restrict__ col, const float* __restrict__ ew,
                           float* __restrict__ deg, int* __restrict__ cnt, int E) {
    int e = blockIdx.x * blockDim.x + threadIdx.x;
    if (e < E) {
        int c = col[e];
        atomicAdd(&deg[c], ew[e]);
        atomicAdd(&cnt[c], 1);
    }
}

__global__ void k_dinv(const float* __restrict__ deg, float* __restrict__ dinv, int n) {
    int i = blockIdx.x * blockDim.x + threadIdx.x;
    if (i < n) {
        float d = deg[i];
        dinv[i] = (d > 0.0f) ? rsqrtf(d) : 0.0f;
    }
}

// ---------------- 3-phase scan ----------------

__global__ void __launch_bounds__(SCAN_B) k_scan_local(
    const int* __restrict__ cnt, int* __restrict__ rowptr,
    int* __restrict__ bsum, int n)
{
    __shared__ int s[SCAN_B];
    const int tid = threadIdx.x;
    const int i = blockIdx.x * SCAN_B + tid;
    int v = (i < n) ? cnt[i] : 0;
    s[tid] = v;
    __syncthreads();
#pragma unroll
    for (int ofs = 1; ofs < SCAN_B; ofs <<= 1) {
        int t = (tid >= ofs) ? s[tid - ofs] : 0;
        __syncthreads();
        s[tid] += t;
        __syncthreads();
    }
    if (i < n) rowptr[i] = s[tid] - v;
    if (tid == SCAN_B - 1) bsum[blockIdx.x] = s[tid];
}

__global__ void __launch_bounds__(MAXBLK) k_scan_mid(
    const int* __restrict__ bsum, int* __restrict__ boffs, int nb)
{
    __shared__ int s[MAXBLK];
    const int tid = threadIdx.x;
    int v = (tid < nb) ? bsum[tid] : 0;
    s[tid] = v;
    __syncthreads();
#pragma unroll
    for (int ofs = 1; ofs < MAXBLK; ofs <<= 1) {
        int t = (tid >= ofs) ? s[tid - ofs] : 0;
        __syncthreads();
        s[tid] += t;
        __syncthreads();
    }
    if (tid < nb) boffs[tid] = s[tid] - v;
}

__global__ void __launch_bounds__(SCAN_B) k_scan_add(
    int* __restrict__ rowptr, const int* __restrict__ boffs, int n, int E)
{
    const int i = blockIdx.x * SCAN_B + threadIdx.x;
    if (i < n) rowptr[i] += boffs[blockIdx.x];
    if (i == 0) rowptr[n] = E;
}

// ---------------- counting-sort fill ----------------

__global__ void k_fill(const int* __restrict__ row, const int* __restrict__ col,
                       const float* __restrict__ ew, const float* __restrict__ dinv,
                       const int* __restrict__ rowptr, int* __restrict__ cur,
                       int* __restrict__ srow, float* __restrict__ snorm, int E) {
    int e = blockIdx.x * blockDim.x + threadIdx.x;
    if (e >= E) return;
    int r = row[e];
    int c = col[e];
    int pos = rowptr[c] + atomicAdd(&cur[c], 1);
    srow[pos] = r;
    snorm[pos] = dinv[r] * ew[e] * dinv[c];
}

// ---------------- weight prep ----------------

__device__ __forceinline__ void wprep_one(const float* W, __nv_bfloat16* dhi,
                                          __nv_bfloat16* dlo, int idx) {
    int n = idx >> 7, k = idx & 127;
    float w = W[k * 128 + n];                 // B[n][k] = W[k][n]
    __nv_bfloat16 hi = __float2bfloat16(w);
    __nv_bfloat16 lo = __float2bfloat16(w - __bfloat162float(hi));
    dhi[n * 128 + k] = hi;
    dlo[n * 128 + k] = lo;
}

__global__ void k_wprep(const float* __restrict__ W, __nv_bfloat16* __restrict__ dhi,
                        __nv_bfloat16* __restrict__ dlo) {
    int idx = blockIdx.x * blockDim.x + threadIdx.x;
    if (idx >= 16384) return;
    wprep_one(W, dhi, dlo, idx);
}

// merged prep for W1..W3, Wout (blockIdx.y selects)
__global__ void k_wprep4(const float* __restrict__ W1, const float* __restrict__ W2,
                         const float* __restrict__ W3, const float* __restrict__ W4,
                         __nv_bfloat16* __restrict__ hbase, __nv_bfloat16* __restrict__ lbase) {
    int idx = blockIdx.x * blockDim.x + threadIdx.x;
    if (idx >= 16384) return;
    const float* W = (blockIdx.y == 0) ? W1 : (blockIdx.y == 1) ? W2
                   : (blockIdx.y == 2) ? W3 : W4;
    int ofs = (blockIdx.y + 1) * 16384;
    wprep_one(W, hbase + ofs, lbase + ofs, idx);
}

// ---------------- HMMA GEMM: C[M,128] = Asplit @ W (+bias) ----------------
// A arrives pre-split (hi/lo bf16). Pure cp.async staging, term-fused mainloop.

__global__ void __launch_bounds__(256, 2) k_gemm_mma(
    const __nv_bfloat16* __restrict__ Ahi, const __nv_bfloat16* __restrict__ Alo,
    const __nv_bfloat16* __restrict__ whi, const __nv_bfloat16* __restrict__ wlo,
    const float* __restrict__ bias, float* __restrict__ C, int M, int doBias)
{
    extern __shared__ char sm[];
    char* sAhi = sm;                  // 16KB
    char* sAlo = sm + 16384;          // 16KB
    char* sWhi = sm + 32768;          // 32KB
    char* sWlo = sm + 65536;          // 32KB

    const int tid = threadIdx.x;
    const int wid = tid >> 5;
    const int lane = tid & 31;
    const int rbase = blockIdx.x * BM;

    const uint32_t uWhi = smem_u32(sWhi);
    const uint32_t uWlo = smem_u32(sWlo);
    const uint32_t uAhi = smem_u32(sAhi);
    const uint32_t uAlo = smem_u32(sAlo);

    // W staging: 128 rows x 16 chunks per buffer
    for (int i = tid; i < 2048; i += 256) {
        int r = i >> 4, c = i & 15;
        uint32_t doff = (uint32_t)((r << 8) + ((c ^ (r & 7)) << 4));
        cp16(uWhi + doff, whi + r * 128 + c * 8);
        cp16(uWlo + doff, wlo + r * 128 + c * 8);
    }
    // A staging: 64 rows x 16 chunks per buffer (pure async, no math)
    for (int i = tid; i < 1024; i += 256) {
        int r = i >> 4, c = i & 15;
        int grow = rbase + r;
        if (grow < M) {   // OOB rows left as garbage; masked at C store
            uint32_t doff = (uint32_t)((r << 8) + ((c ^ (r & 7)) << 4));
            const size_t gofs = (size_t)grow * FDIM + c * 8;
            cp16(uAhi + doff, Ahi + gofs);
            cp16(uAlo + doff, Alo + gofs);
        }
    }
    asm volatile("cp.async.commit_group;" ::: "memory");
    asm volatile("cp.async.wait_group 0;" ::: "memory");
    __syncthreads();

    const int warpRow = (wid & 1) * 32;
    const int warpCol = (wid >> 1) * 32;
    const int a_r = lane & 15;
    const int a_k = (lane >> 4) << 3;
    const int b_n = (lane & 7) + ((lane >> 4) << 3);
    const int b_k = ((lane >> 3) & 1) << 3;

    float c[2][4][4];
#pragma unroll
    for (int mi = 0; mi < 2; mi++)
#pragma unroll
        for (int ni = 0; ni < 4; ni++)
#pragma unroll
            for (int q = 0; q < 4; q++) c[mi][ni][q] = 0.0f;

    uint32_t ah0[2][4], ah1[2][4], al0[2][4], al1[2][4];
    uint32_t bh0[2][4], bh1[2][4], bl0[2][4], bl1[2][4];

#define LOADK(buf, k0)                                                          \
    do {                                                                        \
        ldsm4(ah0[buf][0], ah0[buf][1], ah0[buf][2], ah0[buf][3],               \
              uAhi + swz(warpRow + a_r,      (k0) + a_k));                      \
        ldsm4(ah1[buf][0], ah1[buf][1], ah1[buf][2], ah1[buf][3],               \
              uAhi + swz(warpRow + 16 + a_r, (k0) + a_k));                      \
        ldsm4(al0[buf][0], al0[buf][1], al0[buf][2], al0[buf][3],               \
              uAlo + swz(warpRow + a_r,      (k0) + a_k));                      \
        ldsm4(al1[buf][0], al1[buf][1], al1[buf][2], al1[buf][3],               \
              uAlo + swz(warpRow + 16 + a_r, (k0) + a_k));                      \
        ldsm4(bh0[buf][0], bh0[buf][1], bh0[buf][2], bh0[buf][3],               \
              uWhi + swz(warpCol + b_n,      (k0) + b_k));                      \
        ldsm4(bh1[buf][0], bh1[buf][1], bh1[buf][2], bh1[buf][3],               \
              uWhi + swz(warpCol + 16 + b_n, (k0) + b_k));                      \
        ldsm4(bl0[buf][0], bl0[buf][1], bl0[buf][2], bl0[buf][3],               \
              uWlo + swz(warpCol + b_n,      (k0) + b_k));                      \
        ldsm4(bl1[buf][0], bl1[buf][1], bl1[buf][2], bl1[buf][3],               \
              uWlo + swz(warpCol + 16 + b_n, (k0) + b_k));                      \
    } while (0)

    LOADK(0, 0);
#pragma unroll
    for (int it = 0; it < 8; it++) {
        const int cur = it & 1, nxt = cur ^ 1;
        if (it < 7) LOADK(nxt, (it + 1) << 4);
        mma16816(c[0][0], ah0[cur], bh0[cur][0], bh0[cur][1]);
        mma16816(c[0][1], ah0[cur], bh0[cur][2], bh0[cur][3]);
        mma16816(c[0][2], ah0[cur], bh1[cur][0], bh1[cur][1]);
        mma16816(c[0][3], ah0[cur], bh1[cur][2], bh1[cur][3]);
        mma16816(c[1][0], ah1[cur], bh0[cur][0], bh0[cur][1]);
        mma16816(c[1][1], ah1[cur], bh0[cur][2], bh0[cur][3]);
        mma16816(c[1][2], ah1[cur], bh1[cur][0], bh1[cur][1]);
        mma16816(c[1][3], ah1[cur], bh1[cur][2], bh1[cur][3]);
        mma16816(c[0][0], al0[cur], bh0[cur][0], bh0[cur][1]);
        mma16816(c[0][1], al0[cur], bh0[cur][2], bh0[cur][3]);
        mma16816(c[0][2], al0[cur], bh1[cur][0], bh1[cur][1]);
        mma16816(c[0][3], al0[cur], bh1[cur][2], bh1[cur][3]);
        mma16816(c[1][0], al1[cur], bh0[cur][0], bh0[cur][1]);
        mma16816(c[1][1], al1[cur], bh0[cur][2], bh0[cur][3]);
        mma16816(c[1][2], al1[cur], bh1[cur][0], bh1[cur][1]);
        mma16816(c[1][3], al1[cur], bh1[cur][2], bh1[cur][3]);
        mma16816(c[0][0], ah0[cur], bl0[cur][0], bl0[cur][1]);
        mma16816(c[0][1], ah0[cur], bl0[cur][2], bl0[cur][3]);
        mma16816(c[0][2], ah0[cur], bl1[cur][0], bl1[cur][1]);
        mma16816(c[0][3], ah0[cur], bl1[cur][2], bl1[cur][3]);
        mma16816(c[1][0], ah1[cur], bl0[cur][0], bl0[cur][1]);
        mma16816(c[1][1], ah1[cur], bl0[cur][2], bl0[cur][3]);
        mma16816(c[1][2], ah1[cur], bl1[cur][0], bl1[cur][1]);
        mma16816(c[1][3], ah1[cur], bl1[cur][2], bl1[cur][3]);
    }
#undef LOADK

    const int crow = lane >> 2;
    const int ccol = (lane & 3) * 2;
#pragma unroll
    for (int mi = 0; mi < 2; mi++) {
#pragma unroll
        for (int ni = 0; ni < 4; ni++) {
            int colg = warpCol + ni * 8 + ccol;
            float bx = 0.f, by = 0.f;
            if (doBias) { bx = bias[colg]; by = bias[colg + 1]; }
            int r0 = rbase + warpRow + mi * 16 + crow;
            int r1 = r0 + 8;
            if (r0 < M) {
                float2 v = make_float2(c[mi][ni][0] + bx, c[mi][ni][1] + by);
                *reinterpret_cast<float2*>(C + (size_t)r0 * FDIM + colg) = v;
            }
            if (r1 < M) {
                float2 v = make_float2(c[mi][ni][2] + bx, c[mi][ni][3] + by);
                *reinterpret_cast<float2*>(C + (size_t)r1 * FDIM + colg) = v;
            }
        }
    }
}

// ---------------- CSR aggregate: one warp per node -> split bf16 out ----------------
// hhi/hlo = split bf16 of (optional relu of) [t*dinv^2 + bias + sum norm*t[src]]

__global__ void __launch_bounds__(256) k_aggregate(
    const int* __restrict__ rowptr, const int* __restrict__ srow,
    const float* __restrict__ snorm, const float* __restrict__ dinv,
    const float* __restrict__ bias, const float* __restrict__ t,
    __nv_bfloat16* __restrict__ hhi, __nv_bfloat16* __restrict__ hlo,
    int n, int doRelu)
{
    int node = blockIdx.x * 8 + (threadIdx.x >> 5);
    if (node >= n) return;
    const int lane = threadIdx.x & 31;
    const int f4 = lane * 4;

    float d = __ldg(dinv + node);
    float d2 = d * d;
    float4 tv = *reinterpret_cast<const float4*>(t + (size_t)node * FDIM + f4);
    float4 bv = *reinterpret_cast<const float4*>(bias + f4);
    float4 acc;
    acc.x = fmaf(tv.x, d2, bv.x);
    acc.y = fmaf(tv.y, d2, bv.y);
    acc.z = fmaf(tv.z, d2, bv.z);
    acc.w = fmaf(tv.w, d2, bv.w);

    int j = __ldg(rowptr + node);
    const int jend = __ldg(rowptr + node + 1);

    for (; j + 3 < jend; j += 4) {
        int r0 = __ldg(srow + j);
        int r1 = __ldg(srow + j + 1);
        int r2 = __ldg(srow + j + 2);
        int r3 = __ldg(srow + j + 3);
        float w0 = __ldg(snorm + j);
        float w1 = __ldg(snorm + j + 1);
        float w2 = __ldg(snorm + j + 2);
        float w3 = __ldg(snorm + j + 3);
        float4 v0 = *reinterpret_cast<const float4*>(t + (size_t)r0 * FDIM + f4);
        float4 v1 = *reinterpret_cast<const float4*>(t + (size_t)r1 * FDIM + f4);
        float4 v2 = *reinterpret_cast<const float4*>(t + (size_t)r2 * FDIM + f4);
        float4 v3 = *reinterpret_cast<const float4*>(t + (size_t)r3 * FDIM + f4);
        acc.x = fmaf(v0.x, w0, acc.x); acc.y = fmaf(v0.y, w0, acc.y);
        acc.z = fmaf(v0.z, w0, acc.z); acc.w = fmaf(v0.w, w0, acc.w);
        acc.x = fmaf(v1.x, w1, acc.x); acc.y = fmaf(v1.y, w1, acc.y);
        acc.z = fmaf(v1.z, w1, acc.z); acc.w = fmaf(v1.w, w1, acc.w);
        acc.x = fmaf(v2.x, w2, acc.x); acc.y = fmaf(v2.y, w2, acc.y);
        acc.z = fmaf(v2.z, w2, acc.z); acc.w = fmaf(v2.w, w2, acc.w);
        acc.x = fmaf(v3.x, w3, acc.x); acc.y = fmaf(v3.y, w3, acc.y);
        acc.z = fmaf(v3.z, w3, acc.z); acc.w = fmaf(v3.w, w3, acc.w);
    }
    for (; j < jend; j++) {
        int r0 = __ldg(srow + j);
        float w0 = __ldg(snorm + j);
        float4 v0 = *reinterpret_cast<const float4*>(t + (size_t)r0 * FDIM + f4);
        acc.x = fmaf(v0.x, w0, acc.x); acc.y = fmaf(v0.y, w0, acc.y);
        acc.z = fmaf(v0.z, w0, acc.z); acc.w = fmaf(v0.w, w0, acc.w);
    }

    if (doRelu) {
        acc.x = fmaxf(acc.x, 0.f); acc.y = fmaxf(acc.y, 0.f);
        acc.z = fmaxf(acc.z, 0.f); acc.w = fmaxf(acc.w, 0.f);
    }
    uint32_t h01 = bfpack(acc.x, acc.y);
    uint32_t h23 = bfpack(acc.z, acc.w);
    uint32_t l01 = bfpack(acc.x - bflo(h01), acc.y - bfhi(h01));
    uint32_t l23 = bfpack(acc.z - bflo(h23), acc.w - bfhi(h23));
    const size_t o = (size_t)node * FDIM + f4;
    *reinterpret_cast<uint2*>(hhi + o) = make_uint2(h01, h23);
    *reinterpret_cast<uint2*>(hlo + o) = make_uint2(l01, l23);
}

// ---------------- launch ----------------

extern "C" void kernel_launch(void* const* d_in, const int* in_sizes, int n_in,
                              void* d_out, int out_size) {
    const float* x    = (const float*)d_in[0];
    const int*   ei   = (const int*)  d_in[1];
    const float* ew   = (const float*)d_in[2];
    const float* Wc[4] = {(const float*)d_in[3], (const float*)d_in[5],
                          (const float*)d_in[7], (const float*)d_in[9]};
    const float* bc[4] = {(const float*)d_in[4], (const float*)d_in[6],
                          (const float*)d_in[8], (const float*)d_in[10]};
    const float* Wout = (const float*)d_in[11];
    const float* bout = (const float*)d_in[12];
    float* out = (float*)d_out;

    const int N = in_sizes[0] / FDIM;
    const int E = in_sizes[2];
    const int* rowp = ei;
    const int* colp = ei + E;

    float *t, *deg, *dinv, *snorm;
    int *cnt, *rowptr, *cur, *srow, *bsum, *boffs;
    __nv_bfloat16 *whi, *wlo, *hhi, *hlo, *xhi, *xlo;
    cudaGetSymbolAddress((void**)&t, g_t);
    cudaGetSymbolAddress((void**)&deg, g_deg);
    cudaGetSymbolAddress((void**)&dinv, g_dinv);
    cudaGetSymbolAddress((void**)&cnt, g_cnt);
    cudaGetSymbolAddress((void**)&rowptr, g_rowptr);
    cudaGetSymbolAddress((void**)&cur, g_cursor);
    cudaGetSymbolAddress((void**)&srow, g_srow);
    cudaGetSymbolAddress((void**)&snorm, g_snorm);
    cudaGetSymbolAddress((void**)&bsum, g_bsum);
    cudaGetSymbolAddress((void**)&boffs, g_boffs);
    cudaGetSymbolAddress((void**)&whi, g_whi);
    cudaGetSymbolAddress((void**)&wlo, g_wlo);
    cudaGetSymbolAddress((void**)&hhi, g_hhi);
    cudaGetSymbolAddress((void**)&hlo, g_hlo);
    cudaGetSymbolAddress((void**)&xhi, g_xhi);
    cudaGetSymbolAddress((void**)&xlo, g_xlo);

    static const int SMEM_DYN = 98304;
    cudaFuncSetAttribute(k_gemm_mma, cudaFuncAttributeMaxDynamicSharedMemorySize, SMEM_DYN);

    const int TB = 256;
    const int nScanBlk = (N + SCAN_B - 1) / SCAN_B;
    const int wpBlocks = (16384 + TB - 1) / TB;
    const int gemmBlocks = (N + BM - 1) / BM;
    const int aggBlocks  = (N + 7) / 8;
    const int xpBlocks   = (N * 32 + TB - 1) / TB;

    // Launch order: k_gemm_mma is launch #4 (ncu captures my 4th launch).
    k_wprep<<<wpBlocks, TB>>>(Wc[0], whi, wlo);                                // 1
    k_xprep<<<xpBlocks, TB>>>(x, xhi, xlo, N * 32);                            // 2
    k_init<<<(N + TB - 1) / TB, TB>>>(deg, cnt, cur, N);                       // 3
    k_gemm_mma<<<gemmBlocks, TB, SMEM_DYN>>>(xhi, xlo, whi, wlo,
                                             nullptr, t, N, 0);                // 4 <- profiled
    k_deg_hist<<<(E + TB - 1) / TB, TB>>>(colp, ew, deg, cnt, E);              // 5
    k_dinv<<<(N + TB - 1) / TB, TB>>>(deg, dinv, N);                           // 6
    k_scan_local<<<nScanBlk, SCAN_B>>>(cnt, rowptr, bsum, N);                  // 7
    k_scan_mid<<<1, MAXBLK>>>(bsum, boffs, nScanBlk);                          // 8
    k_scan_add<<<nScanBlk, SCAN_B>>>(rowptr, boffs, N, E);                     // 9
    k_fill<<<(E + TB - 1) / TB, TB>>>(rowp, colp, ew, dinv, rowptr, cur, srow, snorm, E);
    {
        dim3 wg(wpBlocks, 4);
        k_wprep4<<<wg, TB>>>(Wc[1], Wc[2], Wc[3], Wout, whi, wlo);
    }

    // layer 0 aggregate (relu for next conv), then layers 1-3
    k_aggregate<<<aggBlocks, TB>>>(rowptr, srow, snorm, dinv, bc[0], t,
                                   hhi, hlo, N, 1);
    for (int l = 1; l < 4; l++) {
        k_gemm_mma<<<gemmBlocks, TB, SMEM_DYN>>>(hhi, hlo,
                                                 whi + l * 16384, wlo + l * 16384,
                                                 nullptr, t, N, 0);
        k_aggregate<<<aggBlocks, TB>>>(rowptr, srow, snorm, dinv, bc[l], t,
                                       hhi, hlo, N, (l < 3) ? 1 : 0);
    }

    k_gemm_mma<<<gemmBlocks, TB, SMEM_DYN>>>(hhi, hlo,
                                             whi + 4 * 16384, wlo + 4 * 16384,
                                             bout, out, N, 1);
}

// round 11
// speedup vs baseline: 1.8489x; 1.1223x over previous
#include <cuda_runtime.h>
#include <cuda_bf16.h>
#include <cuda_fp16.h>
#include <cstdint>

// ---------------------------------------------------------------------------
// GCN: 4x GCNConv(128->128) + output linear(128->128), N=100000, E=1600000.
// Round 11: conv GEMMs write t as fp16 -> aggregate gathers 256B/row (was
// 512B). Aggregate was ~57us each at the L2 gather cap; bytes is the lever.
// ---------------------------------------------------------------------------

#define NMAX 100096
#define EMAX 1600000
#define FDIM 128
#define SCAN_B 1024
#define MAXBLK 128
#define BM 64

__device__ __align__(16) __half g_t16[(size_t)NMAX * FDIM];     // conv GEMM out (fp16)
__device__ __align__(16) __nv_bfloat16 g_hhi[(size_t)NMAX * FDIM];
__device__ __align__(16) __nv_bfloat16 g_hlo[(size_t)NMAX * FDIM];
__device__ __align__(16) __nv_bfloat16 g_xhi[(size_t)NMAX * FDIM];
__device__ __align__(16) __nv_bfloat16 g_xlo[(size_t)NMAX * FDIM];
__device__ float g_deg[NMAX];
__device__ float g_dinv[NMAX];
__device__ int   g_cnt[NMAX];
__device__ int   g_rowptr[NMAX + 1];
__device__ int   g_cursor[NMAX];
__device__ int   g_srow[EMAX];
__device__ float g_snorm[EMAX];
__device__ int   g_bsum[MAXBLK];
__device__ int   g_boffs[MAXBLK];
__device__ __align__(16) __nv_bfloat16 g_whi[5 * 16384];
__device__ __align__(16) __nv_bfloat16 g_wlo[5 * 16384];

// ---------------- helpers ----------------

__device__ __forceinline__ uint32_t smem_u32(const void* p) {
    uint32_t a;
    asm("{ .reg .u64 t; cvta.to.shared.u64 t, %1; cvt.u32.u64 %0, t; }" : "=r"(a) : "l"(p));
    return a;
}

__device__ __forceinline__ void ldsm4(uint32_t& r0, uint32_t& r1, uint32_t& r2,
                                      uint32_t& r3, uint32_t addr) {
    asm volatile("ldmatrix.sync.aligned.m8n8.x4.shared.b16 {%0,%1,%2,%3}, [%4];"
                 : "=r"(r0), "=r"(r1), "=r"(r2), "=r"(r3) : "r"(addr));
}

__device__ __forceinline__ void mma16816(float* c, const uint32_t* a,
                                         uint32_t b0, uint32_t b1) {
    asm volatile(
        "mma.sync.aligned.m16n8k16.row.col.f32.bf16.bf16.f32 "
        "{%0,%1,%2,%3}, {%4,%5,%6,%7}, {%8,%9}, {%0,%1,%2,%3};"
        : "+f"(c[0]), "+f"(c[1]), "+f"(c[2]), "+f"(c[3])
        : "r"(a[0]), "r"(a[1]), "r"(a[2]), "r"(a[3]), "r"(b0), "r"(b1));
}

__device__ __forceinline__ void cp16(uint32_t dst, const void* src) {
    asm volatile("cp.async.ca.shared.global [%0], [%1], 16;" :: "r"(dst), "l"(src));
}

// XOR-swizzled: 256B rows (128 bf16); addr(r,k) = r*256 + ((k>>3)^(r&7))*16 + (k&7)*2
__device__ __forceinline__ uint32_t swz(int r, int k) {
    return (uint32_t)((r << 8) + ((((k >> 3) ^ (r & 7)) << 4)) + ((k & 7) << 1));
}

__device__ __forceinline__ uint32_t bfpack(float a, float b) {
    __nv_bfloat162 v;
    v.x = __float2bfloat16(a);
    v.y = __float2bfloat16(b);
    return *reinterpret_cast<uint32_t*>(&v);
}
__device__ __forceinline__ float bflo(uint32_t p) {
    __nv_bfloat162 v = *reinterpret_cast<__nv_bfloat162*>(&p);
    return __bfloat162float(v.x);
}
__device__ __forceinline__ float bfhi(uint32_t p) {
    __nv_bfloat162 v = *reinterpret_cast<__nv_bfloat162*>(&p);
    return __bfloat162float(v.y);
}

// ---------------- x prep: fp32 -> hi/lo bf16 ----------------

__global__ void k_xprep(const float* __restrict__ x, __nv_bfloat16* __restrict__ xhi,
                        __nv_bfloat16* __restrict__ xlo, int total4) {
    int i = blockIdx.x * blockDim.x + threadIdx.x;
    if (i >= total4) return;
    float4 v = reinterpret_cast<const float4*>(x)[i];
    uint32_t h01 = bfpack(v.x, v.y);
    uint32_t h23 = bfpack(v.z, v.w);
    uint32_t l01 = bfpack(v.x - bflo(h01), v.y - bfhi(h01));
    uint32_t l23 = bfpack(v.z - bflo(h23), v.w - bfhi(h23));
    reinterpret_cast<uint2*>(xhi)[i] = make_uint2(h01, h23);
    reinterpret_cast<uint2*>(xlo)[i] = make_uint2(l01, l23);
}

// ---------------- degree + histogram ----------------

__global__ void k_init(float* __restrict__ deg, int* __restrict__ cnt,
                       int* __restrict__ cur, int n) {
    int i = blockIdx.x * blockDim.x + threadIdx.x;
    if (i < n) { deg[i] = 1.0f; cnt[i] = 0; cur[i] = 0; }
}

__global__ void k_deg_hist(const int* __restrict__ col, const float* __restrict__ ew,
                           float* __restrict__ deg, int* __restrict__ cnt, int E) {
    int e = blockIdx.x * blockDim.x + threadIdx.x;
    if (e < E) {
        int c = col[e];
        atomicAdd(&deg[c], ew[e]);
        atomicAdd(&cnt[c], 1);
    }
}

__global__ void k_dinv(const float* __restrict__ deg, float* __restrict__ dinv, int n) {
    int i = blockIdx.x * blockDim.x + threadIdx.x;
    if (i < n) {
        float d = deg[i];
        dinv[i] = (d > 0.0f) ? rsqrtf(d) : 0.0f;
    }
}

// ---------------- 3-phase scan ----------------

__global__ void __launch_bounds__(SCAN_B) k_scan_local(
    const int* __restrict__ cnt, int* __restrict__ rowptr,
    int* __restrict__ bsum, int n)
{
    __shared__ int s[SCAN_B];
    const int tid = threadIdx.x;
    const int i = blockIdx.x * SCAN_B + tid;
    int v = (i < n) ? cnt[i] : 0;
    s[tid] = v;
    __syncthreads();
#pragma unroll
    for (int ofs = 1; ofs < SCAN_B; ofs <<= 1) {
        int t = (tid >= ofs) ? s[tid - ofs] : 0;
        __syncthreads();
        s[tid] += t;
        __syncthreads();
    }
    if (i < n) rowptr[i] = s[tid] - v;
    if (tid == SCAN_B - 1) bsum[blockIdx.x] = s[tid];
}

__global__ void __launch_bounds__(MAXBLK) k_scan_mid(
    const int* __restrict__ bsum, int* __restrict__ boffs, int nb)
{
    __shared__ int s[MAXBLK];
    const int tid = threadIdx.x;
    int v = (tid < nb) ? bsum[tid] : 0;
    s[tid] = v;
    __syncthreads();
#pragma unroll
    for (int ofs = 1; ofs < MAXBLK; ofs <<= 1) {
        int t = (tid >= ofs) ? s[tid - ofs] : 0;
        __syncthreads();
        s[tid] += t;
        __syncthreads();
    }
    if (tid < nb) boffs[tid] = s[tid] - v;
}

__global__ void __launch_bounds__(SCAN_B) k_scan_add(
    int* __restrict__ rowptr, const int* __restrict__ boffs, int n, int E)
{
    const int i = blockIdx.x * SCAN_B + threadIdx.x;
    if (i < n) rowptr[i] += boffs[blockIdx.x];
    if (i == 0) rowptr[n] = E;
}

// ---------------- counting-sort fill ----------------

__global__ void k_fill(const int* __restrict__ row, const int* __restrict__ col,
                       const float* __restrict__ ew, const float* __restrict__ dinv,
                       const int* __restrict__ rowptr, int* __restrict__ cur,
                       int* __restrict__ srow, float* __restrict__ snorm, int E) {
    int e = blockIdx.x * blockDim.x + threadIdx.x;
    if (e >= E) return;
    int r = row[e];
    int c = col[e];
    int pos = rowptr[c] + atomicAdd(&cur[c], 1);
    srow[pos] = r;
    snorm[pos] = dinv[r] * ew[e] * dinv[c];
}

// ---------------- weight prep ----------------

__device__ __forceinline__ void wprep_one(const float* W, __nv_bfloat16* dhi,
                                          __nv_bfloat16* dlo, int idx) {
    int n = idx >> 7, k = idx & 127;
    float w = W[k * 128 + n];                 // B[n][k] = W[k][n]
    __nv_bfloat16 hi = __float2bfloat16(w);
    __nv_bfloat16 lo = __float2bfloat16(w - __bfloat162float(hi));
    dhi[n * 128 + k] = hi;
    dlo[n * 128 + k] = lo;
}

__global__ void k_wprep(const float* __restrict__ W, __nv_bfloat16* __restrict__ dhi,
                        __nv_bfloat16* __restrict__ dlo) {
    int idx = blockIdx.x * blockDim.x + threadIdx.x;
    if (idx >= 16384) return;
    wprep_one(W, dhi, dlo, idx);
}

__global__ void k_wprep4(const float* __restrict__ W1, const float* __restrict__ W2,
                         const float* __restrict__ W3, const float* __restrict__ W4,
                         __nv_bfloat16* __restrict__ hbase, __nv_bfloat16* __restrict__ lbase) {
    int idx = blockIdx.x * blockDim.x + threadIdx.x;
    if (idx >= 16384) return;
    const float* W = (blockIdx.y == 0) ? W1 : (blockIdx.y == 1) ? W2
                   : (blockIdx.y == 2) ? W3 : W4;
    int ofs = (blockIdx.y + 1) * 16384;
    wprep_one(W, hbase + ofs, lbase + ofs, idx);
}

// ---------------- HMMA GEMM: Asplit @ W -> fp16 t  OR  fp32 out (+bias) ----------------

__global__ void __launch_bounds__(256, 2) k_gemm_mma(
    const __nv_bfloat16* __restrict__ Ahi, const __nv_bfloat16* __restrict__ Alo,
    const __nv_bfloat16* __restrict__ whi, const __nv_bfloat16* __restrict__ wlo,
    const float* __restrict__ bias, __half* __restrict__ Ch,
    float* __restrict__ Cf, int M, int outFloat)
{
    extern __shared__ char sm[];
    char* sAhi = sm;
    char* sAlo = sm + 16384;
    char* sWhi = sm + 32768;
    char* sWlo = sm + 65536;

    const int tid = threadIdx.x;
    const int wid = tid >> 5;
    const int lane = tid & 31;
    const int rbase = blockIdx.x * BM;

    const uint32_t uWhi = smem_u32(sWhi);
    const uint32_t uWlo = smem_u32(sWlo);
    const uint32_t uAhi = smem_u32(sAhi);
    const uint32_t uAlo = smem_u32(sAlo);

    for (int i = tid; i < 2048; i += 256) {
        int r = i >> 4, c = i & 15;
        uint32_t doff = (uint32_t)((r << 8) + ((c ^ (r & 7)) << 4));
        cp16(uWhi + doff, whi + r * 128 + c * 8);
        cp16(uWlo + doff, wlo + r * 128 + c * 8);
    }
    for (int i = tid; i < 1024; i += 256) {
        int r = i >> 4, c = i & 15;
        int grow = rbase + r;
        if (grow < M) {
            uint32_t doff = (uint32_t)((r << 8) + ((c ^ (r & 7)) << 4));
            const size_t gofs = (size_t)grow * FDIM + c * 8;
            cp16(uAhi + doff, Ahi + gofs);
            cp16(uAlo + doff, Alo + gofs);
        }
    }
    asm volatile("cp.async.commit_group;" ::: "memory");
    asm volatile("cp.async.wait_group 0;" ::: "memory");
    __syncthreads();

    const int warpRow = (wid & 1) * 32;
    const int warpCol = (wid >> 1) * 32;
    const int a_r = lane & 15;
    const int a_k = (lane >> 4) << 3;
    const int b_n = (lane & 7) + ((lane >> 4) << 3);
    const int b_k = ((lane >> 3) & 1) << 3;

    float c[2][4][4];
#pragma unroll
    for (int mi = 0; mi < 2; mi++)
#pragma unroll
        for (int ni = 0; ni < 4; ni++)
#pragma unroll
            for (int q = 0; q < 4; q++) c[mi][ni][q] = 0.0f;

    uint32_t ah0[2][4], ah1[2][4], al0[2][4], al1[2][4];
    uint32_t bh0[2][4], bh1[2][4], bl0[2][4], bl1[2][4];

#define LOADK(buf, k0)                                                          \
    do {                                                                        \
        ldsm4(ah0[buf][0], ah0[buf][1], ah0[buf][2], ah0[buf][3],               \
              uAhi + swz(warpRow + a_r,      (k0) + a_k));                      \
        ldsm4(ah1[buf][0], ah1[buf][1], ah1[buf][2], ah1[buf][3],               \
              uAhi + swz(warpRow + 16 + a_r, (k0) + a_k));                      \
        ldsm4(al0[buf][0], al0[buf][1], al0[buf][2], al0[buf][3],               \
              uAlo + swz(warpRow + a_r,      (k0) + a_k));                      \
        ldsm4(al1[buf][0], al1[buf][1], al1[buf][2], al1[buf][3],               \
              uAlo + swz(warpRow + 16 + a_r, (k0) + a_k));                      \
        ldsm4(bh0[buf][0], bh0[buf][1], bh0[buf][2], bh0[buf][3],               \
              uWhi + swz(warpCol + b_n,      (k0) + b_k));                      \
        ldsm4(bh1[buf][0], bh1[buf][1], bh1[buf][2], bh1[buf][3],               \
              uWhi + swz(warpCol + 16 + b_n, (k0) + b_k));                      \
        ldsm4(bl0[buf][0], bl0[buf][1], bl0[buf][2], bl0[buf][3],               \
              uWlo + swz(warpCol + b_n,      (k0) + b_k));                      \
        ldsm4(bl1[buf][0], bl1[buf][1], bl1[buf][2], bl1[buf][3],               \
              uWlo + swz(warpCol + 16 + b_n, (k0) + b_k));                      \
    } while (0)

    LOADK(0, 0);
#pragma unroll
    for (int it = 0; it < 8; it++) {
        const int cur = it & 1, nxt = cur ^ 1;
        if (it < 7) LOADK(nxt, (it + 1) << 4);
        mma16816(c[0][0], ah0[cur], bh0[cur][0], bh0[cur][1]);
        mma16816(c[0][1], ah0[cur], bh0[cur][2], bh0[cur][3]);
        mma16816(c[0][2], ah0[cur], bh1[cur][0], bh1[cur][1]);
        mma16816(c[0][3], ah0[cur], bh1[cur][2], bh1[cur][3]);
        mma16816(c[1][0], ah1[cur], bh0[cur][0], bh0[cur][1]);
        mma16816(c[1][1], ah1[cur], bh0[cur][2], bh0[cur][3]);
        mma16816(c[1][2], ah1[cur], bh1[cur][0], bh1[cur][1]);
        mma16816(c[1][3], ah1[cur], bh1[cur][2], bh1[cur][3]);
        mma16816(c[0][0], al0[cur], bh0[cur][0], bh0[cur][1]);
        mma16816(c[0][1], al0[cur], bh0[cur][2], bh0[cur][3]);
        mma16816(c[0][2], al0[cur], bh1[cur][0], bh1[cur][1]);
        mma16816(c[0][3], al0[cur], bh1[cur][2], bh1[cur][3]);
        mma16816(c[1][0], al1[cur], bh0[cur][0], bh0[cur][1]);
        mma16816(c[1][1], al1[cur], bh0[cur][2], bh0[cur][3]);
        mma16816(c[1][2], al1[cur], bh1[cur][0], bh1[cur][1]);
        mma16816(c[1][3], al1[cur], bh1[cur][2], bh1[cur][3]);
        mma16816(c[0][0], ah0[cur], bl0[cur][0], bl0[cur][1]);
        mma16816(c[0][1], ah0[cur], bl0[cur][2], bl0[cur][3]);
        mma16816(c[0][2], ah0[cur], bl1[cur][0], bl1[cur][1]);
        mma16816(c[0][3], ah0[cur], bl1[cur][2], bl1[cur][3]);
        mma16816(c[1][0], ah1[cur], bl0[cur][0], bl0[cur][1]);
        mma16816(c[1][1], ah1[cur], bl0[cur][2], bl0[cur][3]);
        mma16816(c[1][2], ah1[cur], bl1[cur][0], bl1[cur][1]);
        mma16816(c[1][3], ah1[cur], bl1[cur][2], bl1[cur][3]);
    }
#undef LOADK

    const int crow = lane >> 2;
    const int ccol = (lane & 3) * 2;
#pragma unroll
    for (int mi = 0; mi < 2; mi++) {
#pragma unroll
        for (int ni = 0; ni < 4; ni++) {
            int colg = warpCol + ni * 8 + ccol;
            int r0 = rbase + warpRow + mi * 16 + crow;
            int r1 = r0 + 8;
            if (outFloat) {
                float bx = bias[colg], by = bias[colg + 1];
                if (r0 < M) {
                    float2 v = make_float2(c[mi][ni][0] + bx, c[mi][ni][1] + by);
                    *reinterpret_cast<float2*>(Cf + (size_t)r0 * FDIM + colg) = v;
                }
                if (r1 < M) {
                    float2 v = make_float2(c[mi][ni][2] + bx, c[mi][ni][3] + by);
                    *reinterpret_cast<float2*>(Cf + (size_t)r1 * FDIM + colg) = v;
                }
            } else {
                if (r0 < M) {
                    __half2 v = __floats2half2_rn(c[mi][ni][0], c[mi][ni][1]);
                    *reinterpret_cast<__half2*>(Ch + (size_t)r0 * FDIM + colg) = v;
                }
                if (r1 < M) {
                    __half2 v = __floats2half2_rn(c[mi][ni][2], c[mi][ni][3]);
                    *reinterpret_cast<__half2*>(Ch + (size_t)r1 * FDIM + colg) = v;
                }
            }
        }
    }
}

// ---------------- CSR aggregate: fp16 gathers -> split bf16 out ----------------

__global__ void __launch_bounds__(256) k_aggregate(
    const int* __restrict__ rowptr, const int* __restrict__ srow,
    const float* __restrict__ snorm, const float* __restrict__ dinv,
    const float* __restrict__ bias, const __half* __restrict__ t16,
    __nv_bfloat16* __restrict__ hhi, __nv_bfloat16* __restrict__ hlo,
    int n, int doRelu)
{
    int node = blockIdx.x * 8 + (threadIdx.x >> 5);
    if (node >= n) return;
    const int lane = threadIdx.x & 31;
    const int f4 = lane * 4;   // 4 halves = 8B per lane

    float d = __ldg(dinv + node);
    float d2 = d * d;

    uint2 sraw = *reinterpret_cast<const uint2*>(t16 + (size_t)node * FDIM + f4);
    float2 s0 = __half22float2(*reinterpret_cast<__half2*>(&sraw.x));
    float2 s1 = __half22float2(*reinterpret_cast<__half2*>(&sraw.y));
    float4 bv = *reinterpret_cast<const float4*>(bias + f4);
    float4 acc;
    acc.x = fmaf(s0.x, d2, bv.x);
    acc.y = fmaf(s0.y, d2, bv.y);
    acc.z = fmaf(s1.x, d2, bv.z);
    acc.w = fmaf(s1.y, d2, bv.w);

    int j = __ldg(rowptr + node);
    const int jend = __ldg(rowptr + node + 1);

#define GATHER(rj, wj)                                                          \
    do {                                                                        \
        uint2 raw = *reinterpret_cast<const uint2*>(t16 + (size_t)(rj) * FDIM + f4); \
        float2 p0 = __half22float2(*reinterpret_cast<__half2*>(&raw.x));        \
        float2 p1 = __half22float2(*reinterpret_cast<__half2*>(&raw.y));        \
        acc.x = fmaf(p0.x, (wj), acc.x); acc.y = fmaf(p0.y, (wj), acc.y);       \
        acc.z = fmaf(p1.x, (wj), acc.z); acc.w = fmaf(p1.y, (wj), acc.w);       \
    } while (0)

    for (; j + 3 < jend; j += 4) {
        int r0 = __ldg(srow + j);
        int r1 = __ldg(srow + j + 1);
        int r2 = __ldg(srow + j + 2);
        int r3 = __ldg(srow + j + 3);
        float w0 = __ldg(snorm + j);
        float w1 = __ldg(snorm + j + 1);
        float w2 = __ldg(snorm + j + 2);
        float w3 = __ldg(snorm + j + 3);
        GATHER(r0, w0);
        GATHER(r1, w1);
        GATHER(r2, w2);
        GATHER(r3, w3);
    }
    for (; j < jend; j++) {
        int r0 = __ldg(srow + j);
        float w0 = __ldg(snorm + j);
        GATHER(r0, w0);
    }
#undef GATHER

    if (doRelu) {
        acc.x = fmaxf(acc.x, 0.f); acc.y = fmaxf(acc.y, 0.f);
        acc.z = fmaxf(acc.z, 0.f); acc.w = fmaxf(acc.w, 0.f);
    }
    uint32_t h01 = bfpack(acc.x, acc.y);
    uint32_t h23 = bfpack(acc.z, acc.w);
    uint32_t l01 = bfpack(acc.x - bflo(h01), acc.y - bfhi(h01));
    uint32_t l23 = bfpack(acc.z - bflo(h23), acc.w - bfhi(h23));
    const size_t o = (size_t)node * FDIM + f4;
    *reinterpret_cast<uint2*>(hhi + o) = make_uint2(h01, h23);
    *reinterpret_cast<uint2*>(hlo + o) = make_uint2(l01, l23);
}

// ---------------- launch ----------------

extern "C" void kernel_launch(void* const* d_in, const int* in_sizes, int n_in,
                              void* d_out, int out_size) {
    const float* x    = (const float*)d_in[0];
    const int*   ei   = (const int*)  d_in[1];
    const float* ew   = (const float*)d_in[2];
    const float* Wc[4] = {(const float*)d_in[3], (const float*)d_in[5],
                          (const float*)d_in[7], (const float*)d_in[9]};
    const float* bc[4] = {(const float*)d_in[4], (const float*)d_in[6],
                          (const float*)d_in[8], (const float*)d_in[10]};
    const float* Wout = (const float*)d_in[11];
    const float* bout = (const float*)d_in[12];
    float* out = (float*)d_out;

    const int N = in_sizes[0] / FDIM;
    const int E = in_sizes[2];
    const int* rowp = ei;
    const int* colp = ei + E;

    float *deg, *dinv, *snorm;
    int *cnt, *rowptr, *cur, *srow, *bsum, *boffs;
    __half* t16;
    __nv_bfloat16 *whi, *wlo, *hhi, *hlo, *xhi, *xlo;
    cudaGetSymbolAddress((void**)&t16, g_t16);
    cudaGetSymbolAddress((void**)&deg, g_deg);
    cudaGetSymbolAddress((void**)&dinv, g_dinv);
    cudaGetSymbolAddress((void**)&cnt, g_cnt);
    cudaGetSymbolAddress((void**)&rowptr, g_rowptr);
    cudaGetSymbolAddress((void**)&cur, g_cursor);
    cudaGetSymbolAddress((void**)&srow, g_srow);
    cudaGetSymbolAddress((void**)&snorm, g_snorm);
    cudaGetSymbolAddress((void**)&bsum, g_bsum);
    cudaGetSymbolAddress((void**)&boffs, g_boffs);
    cudaGetSymbolAddress((void**)&whi, g_whi);
    cudaGetSymbolAddress((void**)&wlo, g_wlo);
    cudaGetSymbolAddress((void**)&hhi, g_hhi);
    cudaGetSymbolAddress((void**)&hlo, g_hlo);
    cudaGetSymbolAddress((void**)&xhi, g_xhi);
    cudaGetSymbolAddress((void**)&xlo, g_xlo);

    static const int SMEM_DYN = 98304;
    cudaFuncSetAttribute(k_gemm_mma, cudaFuncAttributeMaxDynamicSharedMemorySize, SMEM_DYN);

    const int TB = 256;
    const int nScanBlk = (N + SCAN_B - 1) / SCAN_B;
    const int wpBlocks = (16384 + TB - 1) / TB;
    const int gemmBlocks = (N + BM - 1) / BM;
    const int aggBlocks  = (N + 7) / 8;
    const int xpBlocks   = (N * 32 + TB - 1) / TB;

    // Launch order: k_gemm_mma is launch #4 (ncu captures my 4th launch).
    k_wprep<<<wpBlocks, TB>>>(Wc[0], whi, wlo);                                // 1
    k_xprep<<<xpBlocks, TB>>>(x, xhi, xlo, N * 32);                            // 2
    k_init<<<(N + TB - 1) / TB, TB>>>(deg, cnt, cur, N);                       // 3
    k_gemm_mma<<<gemmBlocks, TB, SMEM_DYN>>>(xhi, xlo, whi, wlo,
                                             nullptr, t16, nullptr, N, 0);     // 4 <- profiled
    k_deg_hist<<<(E + TB - 1) / TB, TB>>>(colp, ew, deg, cnt, E);              // 5
    k_dinv<<<(N + TB - 1) / TB, TB>>>(deg, dinv, N);                           // 6
    k_scan_local<<<nScanBlk, SCAN_B>>>(cnt, rowptr, bsum, N);                  // 7
    k_scan_mid<<<1, MAXBLK>>>(bsum, boffs, nScanBlk);                          // 8
    k_scan_add<<<nScanBlk, SCAN_B>>>(rowptr, boffs, N, E);                     // 9
    k_fill<<<(E + TB - 1) / TB, TB>>>(rowp, colp, ew, dinv, rowptr, cur, srow, snorm, E);
    {
        dim3 wg(wpBlocks, 4);
        k_wprep4<<<wg, TB>>>(Wc[1], Wc[2], Wc[3], Wout, whi, wlo);
    }

    k_aggregate<<<aggBlocks, TB>>>(rowptr, srow, snorm, dinv, bc[0], t16,
                                   hhi, hlo, N, 1);
    for (int l = 1; l < 4; l++) {
        k_gemm_mma<<<gemmBlocks, TB, SMEM_DYN>>>(hhi, hlo,
                                                 whi + l * 16384, wlo + l * 16384,
                                                 nullptr, t16, nullptr, N, 0);
        k_aggregate<<<aggBlocks, TB>>>(rowptr, srow, snorm, dinv, bc[l], t16,
                                       hhi, hlo, N, (l < 3) ? 1 : 0);
    }

    k_gemm_mma<<<gemmBlocks, TB, SMEM_DYN>>>(hhi, hlo,
                                             whi + 4 * 16384, wlo + 4 * 16384,
                                             bout, nullptr, out, N, 1);
}

// round 12
// speedup vs baseline: 1.8701x; 1.0115x over previous
#include <cuda_runtime.h>
#include <cuda_bf16.h>
#include <cuda_fp16.h>
#include <cstdint>

// ---------------------------------------------------------------------------
// GCN: 4x GCNConv(128->128) + output linear(128->128), N=100000, E=1600000.
// Round 12: fork a second stream inside graph capture — CSR build chain
// (~55us) overlaps the wprep/xprep/gemm0 chain (~48us). Kernels unchanged.
// ---------------------------------------------------------------------------

#define NMAX 100096
#define EMAX 1600000
#define FDIM 128
#define SCAN_B 1024
#define MAXBLK 128
#define BM 64

__device__ __align__(16) __half g_t16[(size_t)NMAX * FDIM];
__device__ __align__(16) __nv_bfloat16 g_hhi[(size_t)NMAX * FDIM];
__device__ __align__(16) __nv_bfloat16 g_hlo[(size_t)NMAX * FDIM];
__device__ __align__(16) __nv_bfloat16 g_xhi[(size_t)NMAX * FDIM];
__device__ __align__(16) __nv_bfloat16 g_xlo[(size_t)NMAX * FDIM];
__device__ float g_deg[NMAX];
__device__ float g_dinv[NMAX];
__device__ int   g_cnt[NMAX];
__device__ int   g_rowptr[NMAX + 1];
__device__ int   g_cursor[NMAX];
__device__ int   g_srow[EMAX];
__device__ float g_snorm[EMAX];
__device__ int   g_bsum[MAXBLK];
__device__ int   g_boffs[MAXBLK];
__device__ __align__(16) __nv_bfloat16 g_whi[5 * 16384];
__device__ __align__(16) __nv_bfloat16 g_wlo[5 * 16384];

// ---------------- helpers ----------------

__device__ __forceinline__ uint32_t smem_u32(const void* p) {
    uint32_t a;
    asm("{ .reg .u64 t; cvta.to.shared.u64 t, %1; cvt.u32.u64 %0, t; }" : "=r"(a) : "l"(p));
    return a;
}

__device__ __forceinline__ void ldsm4(uint32_t& r0, uint32_t& r1, uint32_t& r2,
                                      uint32_t& r3, uint32_t addr) {
    asm volatile("ldmatrix.sync.aligned.m8n8.x4.shared.b16 {%0,%1,%2,%3}, [%4];"
                 : "=r"(r0), "=r"(r1), "=r"(r2), "=r"(r3) : "r"(addr));
}

__device__ __forceinline__ void mma16816(float* c, const uint32_t* a,
                                         uint32_t b0, uint32_t b1) {
    asm volatile(
        "mma.sync.aligned.m16n8k16.row.col.f32.bf16.bf16.f32 "
        "{%0,%1,%2,%3}, {%4,%5,%6,%7}, {%8,%9}, {%0,%1,%2,%3};"
        : "+f"(c[0]), "+f"(c[1]), "+f"(c[2]), "+f"(c[3])
        : "r"(a[0]), "r"(a[1]), "r"(a[2]), "r"(a[3]), "r"(b0), "r"(b1));
}

__device__ __forceinline__ void cp16(uint32_t dst, const void* src) {
    asm volatile("cp.async.ca.shared.global [%0], [%1], 16;" :: "r"(dst), "l"(src));
}

__device__ __forceinline__ uint32_t swz(int r, int k) {
    return (uint32_t)((r << 8) + ((((k >> 3) ^ (r & 7)) << 4)) + ((k & 7) << 1));
}

__device__ __forceinline__ uint32_t bfpack(float a, float b) {
    __nv_bfloat162 v;
    v.x = __float2bfloat16(a);
    v.y = __float2bfloat16(b);
    return *reinterpret_cast<uint32_t*>(&v);
}
__device__ __forceinline__ float bflo(uint32_t p) {
    __nv_bfloat162 v = *reinterpret_cast<__nv_bfloat162*>(&p);
    return __bfloat162float(v.x);
}
__device__ __forceinline__ float bfhi(uint32_t p) {
    __nv_bfloat162 v = *reinterpret_cast<__nv_bfloat162*>(&p);
    return __bfloat162float(v.y);
}

// ---------------- x prep ----------------

__global__ void k_xprep(const float* __restrict__ x, __nv_bfloat16* __restrict__ xhi,
                        __nv_bfloat16* __restrict__ xlo, int total4) {
    int i = blockIdx.x * blockDim.x + threadIdx.x;
    if (i >= total4) return;
    float4 v = reinterpret_cast<const float4*>(x)[i];
    uint32_t h01 = bfpack(v.x, v.y);
    uint32_t h23 = bfpack(v.z, v.w);
    uint32_t l01 = bfpack(v.x - bflo(h01), v.y - bfhi(h01));
    uint32_t l23 = bfpack(v.z - bflo(h23), v.w - bfhi(h23));
    reinterpret_cast<uint2*>(xhi)[i] = make_uint2(h01, h23);
    reinterpret_cast<uint2*>(xlo)[i] = make_uint2(l01, l23);
}

// ---------------- degree + histogram ----------------

__global__ void k_init(float* __restrict__ deg, int* __restrict__ cnt,
                       int* __restrict__ cur, int n) {
    int i = blockIdx.x * blockDim.x + threadIdx.x;
    if (i < n) { deg[i] = 1.0f; cnt[i] = 0; cur[i] = 0; }
}

__global__ void k_deg_hist(const int* __restrict__ col, const float* __restrict__ ew,
                           float* __restrict__ deg, int* __restrict__ cnt, int E) {
    int e = blockIdx.x * blockDim.x + threadIdx.x;
    if (e < E) {
        int c = col[e];
        atomicAdd(&deg[c], ew[e]);
        atomicAdd(&cnt[c], 1);
    }
}

__global__ void k_dinv(const float* __restrict__ deg, float* __restrict__ dinv, int n) {
    int i = blockIdx.x * blockDim.x + threadIdx.x;
    if (i < n) {
        float d = deg[i];
        dinv[i] = (d > 0.0f) ? rsqrtf(d) : 0.0f;
    }
}

// ---------------- 3-phase scan ----------------

__global__ void __launch_bounds__(SCAN_B) k_scan_local(
    const int* __restrict__ cnt, int* __restrict__ rowptr,
    int* __restrict__ bsum, int n)
{
    __shared__ int s[SCAN_B];
    const int tid = threadIdx.x;
    const int i = blockIdx.x * SCAN_B + tid;
    int v = (i < n) ? cnt[i] : 0;
    s[tid] = v;
    __syncthreads();
#pragma unroll
    for (int ofs = 1; ofs < SCAN_B; ofs <<= 1) {
        int t = (tid >= ofs) ? s[tid - ofs] : 0;
        __syncthreads();
        s[tid] += t;
        __syncthreads();
    }
    if (i < n) rowptr[i] = s[tid] - v;
    if (tid == SCAN_B - 1) bsum[blockIdx.x] = s[tid];
}

__global__ void __launch_bounds__(MAXBLK) k_scan_mid(
    const int* __restrict__ bsum, int* __restrict__ boffs, int nb)
{
    __shared__ int s[MAXBLK];
    const int tid = threadIdx.x;
    int v = (tid < nb) ? bsum[tid] : 0;
    s[tid] = v;
    __syncthreads();
#pragma unroll
    for (int ofs = 1; ofs < MAXBLK; ofs <<= 1) {
        int t = (tid >= ofs) ? s[tid - ofs] : 0;
        __syncthreads();
        s[tid] += t;
        __syncthreads();
    }
    if (tid < nb) boffs[tid] = s[tid] - v;
}

__global__ void __launch_bounds__(SCAN_B) k_scan_add(
    int* __restrict__ rowptr, const int* __restrict__ boffs, int n, int E)
{
    const int i = blockIdx.x * SCAN_B + threadIdx.x;
    if (i < n) rowptr[i] += boffs[blockIdx.x];
    if (i == 0) rowptr[n] = E;
}

// ---------------- counting-sort fill ----------------

__global__ void k_fill(const int* __restrict__ row, const int* __restrict__ col,
                       const float* __restrict__ ew, const float* __restrict__ dinv,
                       const int* __restrict__ rowptr, int* __restrict__ cur,
                       int* __restrict__ srow, float* __restrict__ snorm, int E) {
    int e = blockIdx.x * blockDim.x + threadIdx.x;
    if (e >= E) return;
    int r = row[e];
    int c = col[e];
    int pos = rowptr[c] + atomicAdd(&cur[c], 1);
    srow[pos] = r;
    snorm[pos] = dinv[r] * ew[e] * dinv[c];
}

// ---------------- weight prep ----------------

__device__ __forceinline__ void wprep_one(const float* W, __nv_bfloat16* dhi,
                                          __nv_bfloat16* dlo, int idx) {
    int n = idx >> 7, k = idx & 127;
    float w = W[k * 128 + n];                 // B[n][k] = W[k][n]
    __nv_bfloat16 hi = __float2bfloat16(w);
    __nv_bfloat16 lo = __float2bfloat16(w - __bfloat162float(hi));
    dhi[n * 128 + k] = hi;
    dlo[n * 128 + k] = lo;
}

__global__ void k_wprep(const float* __restrict__ W, __nv_bfloat16* __restrict__ dhi,
                        __nv_bfloat16* __restrict__ dlo) {
    int idx = blockIdx.x * blockDim.x + threadIdx.x;
    if (idx >= 16384) return;
    wprep_one(W, dhi, dlo, idx);
}

__global__ void k_wprep4(const float* __restrict__ W1, const float* __restrict__ W2,
                         const float* __restrict__ W3, const float* __restrict__ W4,
                         __nv_bfloat16* __restrict__ hbase, __nv_bfloat16* __restrict__ lbase) {
    int idx = blockIdx.x * blockDim.x + threadIdx.x;
    if (idx >= 16384) return;
    const float* W = (blockIdx.y == 0) ? W1 : (blockIdx.y == 1) ? W2
                   : (blockIdx.y == 2) ? W3 : W4;
    int ofs = (blockIdx.y + 1) * 16384;
    wprep_one(W, hbase + ofs, lbase + ofs, idx);
}

// ---------------- HMMA GEMM ----------------

__global__ void __launch_bounds__(256, 2) k_gemm_mma(
    const __nv_bfloat16* __restrict__ Ahi, const __nv_bfloat16* __restrict__ Alo,
    const __nv_bfloat16* __restrict__ whi, const __nv_bfloat16* __restrict__ wlo,
    const float* __restrict__ bias, __half* __restrict__ Ch,
    float* __restrict__ Cf, int M, int outFloat)
{
    extern __shared__ char sm[];
    char* sAhi = sm;
    char* sAlo = sm + 16384;
    char* sWhi = sm + 32768;
    char* sWlo = sm + 65536;

    const int tid = threadIdx.x;
    const int wid = tid >> 5;
    const int lane = tid & 31;
    const int rbase = blockIdx.x * BM;

    const uint32_t uWhi = smem_u32(sWhi);
    const uint32_t uWlo = smem_u32(sWlo);
    const uint32_t uAhi = smem_u32(sAhi);
    const uint32_t uAlo = smem_u32(sAlo);

    for (int i = tid; i < 2048; i += 256) {
        int r = i >> 4, c = i & 15;
        uint32_t doff = (uint32_t)((r << 8) + ((c ^ (r & 7)) << 4));
        cp16(uWhi + doff, whi + r * 128 + c * 8);
        cp16(uWlo + doff, wlo + r * 128 + c * 8);
    }
    for (int i = tid; i < 1024; i += 256) {
        int r = i >> 4, c = i & 15;
        int grow = rbase + r;
        if (grow < M) {
            uint32_t doff = (uint32_t)((r << 8) + ((c ^ (r & 7)) << 4));
            const size_t gofs = (size_t)grow * FDIM + c * 8;
            cp16(uAhi + doff, Ahi + gofs);
            cp16(uAlo + doff, Alo + gofs);
        }
    }
    asm volatile("cp.async.commit_group;" ::: "memory");
    asm volatile("cp.async.wait_group 0;" ::: "memory");
    __syncthreads();

    const int warpRow = (wid & 1) * 32;
    const int warpCol = (wid >> 1) * 32;
    const int a_r = lane & 15;
    const int a_k = (lane >> 4) << 3;
    const int b_n = (lane & 7) + ((lane >> 4) << 3);
    const int b_k = ((lane >> 3) & 1) << 3;

    float c[2][4][4];
#pragma unroll
    for (int mi = 0; mi < 2; mi++)
#pragma unroll
        for (int ni = 0; ni < 4; ni++)
#pragma unroll
            for (int q = 0; q < 4; q++) c[mi][ni][q] = 0.0f;

    uint32_t ah0[2][4], ah1[2][4], al0[2][4], al1[2][4];
    uint32_t bh0[2][4], bh1[2][4], bl0[2][4], bl1[2][4];

#define LOADK(buf, k0)                                                          \
    do {                                                                        \
        ldsm4(ah0[buf][0], ah0[buf][1], ah0[buf][2], ah0[buf][3],               \
              uAhi + swz(warpRow + a_r,      (k0) + a_k));                      \
        ldsm4(ah1[buf][0], ah1[buf][1], ah1[buf][2], ah1[buf][3],               \
              uAhi + swz(warpRow + 16 + a_r, (k0) + a_k));                      \
        ldsm4(al0[buf][0], al0[buf][1], al0[buf][2], al0[buf][3],               \
              uAlo + swz(warpRow + a_r,      (k0) + a_k));                      \
        ldsm4(al1[buf][0], al1[buf][1], al1[buf][2], al1[buf][3],               \
              uAlo + swz(warpRow + 16 + a_r, (k0) + a_k));                      \
        ldsm4(bh0[buf][0], bh0[buf][1], bh0[buf][2], bh0[buf][3],               \
              uWhi + swz(warpCol + b_n,      (k0) + b_k));                      \
        ldsm4(bh1[buf][0], bh1[buf][1], bh1[buf][2], bh1[buf][3],               \
              uWhi + swz(warpCol + 16 + b_n, (k0) + b_k));                      \
        ldsm4(bl0[buf][0], bl0[buf][1], bl0[buf][2], bl0[buf][3],               \
              uWlo + swz(warpCol + b_n,      (k0) + b_k));                      \
        ldsm4(bl1[buf][0], bl1[buf][1], bl1[buf][2], bl1[buf][3],               \
              uWlo + swz(warpCol + 16 + b_n, (k0) + b_k));                      \
    } while (0)

    LOADK(0, 0);
#pragma unroll
    for (int it = 0; it < 8; it++) {
        const int cur = it & 1, nxt = cur ^ 1;
        if (it < 7) LOADK(nxt, (it + 1) << 4);
        mma16816(c[0][0], ah0[cur], bh0[cur][0], bh0[cur][1]);
        mma16816(c[0][1], ah0[cur], bh0[cur][2], bh0[cur][3]);
        mma16816(c[0][2], ah0[cur], bh1[cur][0], bh1[cur][1]);
        mma16816(c[0][3], ah0[cur], bh1[cur][2], bh1[cur][3]);
        mma16816(c[1][0], ah1[cur], bh0[cur][0], bh0[cur][1]);
        mma16816(c[1][1], ah1[cur], bh0[cur][2], bh0[cur][3]);
        mma16816(c[1][2], ah1[cur], bh1[cur][0], bh1[cur][1]);
        mma16816(c[1][3], ah1[cur], bh1[cur][2], bh1[cur][3]);
        mma16816(c[0][0], al0[cur], bh0[cur][0], bh0[cur][1]);
        mma16816(c[0][1], al0[cur], bh0[cur][2], bh0[cur][3]);
        mma16816(c[0][2], al0[cur], bh1[cur][0], bh1[cur][1]);
        mma16816(c[0][3], al0[cur], bh1[cur][2], bh1[cur][3]);
        mma16816(c[1][0], al1[cur], bh0[cur][0], bh0[cur][1]);
        mma16816(c[1][1], al1[cur], bh0[cur][2], bh0[cur][3]);
        mma16816(c[1][2], al1[cur], bh1[cur][0], bh1[cur][1]);
        mma16816(c[1][3], al1[cur], bh1[cur][2], bh1[cur][3]);
        mma16816(c[0][0], ah0[cur], bl0[cur][0], bl0[cur][1]);
        mma16816(c[0][1], ah0[cur], bl0[cur][2], bl0[cur][3]);
        mma16816(c[0][2], ah0[cur], bl1[cur][0], bl1[cur][1]);
        mma16816(c[0][3], ah0[cur], bl1[cur][2], bl1[cur][3]);
        mma16816(c[1][0], ah1[cur], bl0[cur][0], bl0[cur][1]);
        mma16816(c[1][1], ah1[cur], bl0[cur][2], bl0[cur][3]);
        mma16816(c[1][2], ah1[cur], bl1[cur][0], bl1[cur][1]);
        mma16816(c[1][3], ah1[cur], bl1[cur][2], bl1[cur][3]);
    }
#undef LOADK

    const int crow = lane >> 2;
    const int ccol = (lane & 3) * 2;
#pragma unroll
    for (int mi = 0; mi < 2; mi++) {
#pragma unroll
        for (int ni = 0; ni < 4; ni++) {
            int colg = warpCol + ni * 8 + ccol;
            int r0 = rbase + warpRow + mi * 16 + crow;
            int r1 = r0 + 8;
            if (outFloat) {
                float bx = bias[colg], by = bias[colg + 1];
                if (r0 < M) {
                    float2 v = make_float2(c[mi][ni][0] + bx, c[mi][ni][1] + by);
                    *reinterpret_cast<float2*>(Cf + (size_t)r0 * FDIM + colg) = v;
                }
                if (r1 < M) {
                    float2 v = make_float2(c[mi][ni][2] + bx, c[mi][ni][3] + by);
                    *reinterpret_cast<float2*>(Cf + (size_t)r1 * FDIM + colg) = v;
                }
            } else {
                if (r0 < M) {
                    __half2 v = __floats2half2_rn(c[mi][ni][0], c[mi][ni][1]);
                    *reinterpret_cast<__half2*>(Ch + (size_t)r0 * FDIM + colg) = v;
                }
                if (r1 < M) {
                    __half2 v = __floats2half2_rn(c[mi][ni][2], c[mi][ni][3]);
                    *reinterpret_cast<__half2*>(Ch + (size_t)r1 * FDIM + colg) = v;
                }
            }
        }
    }
}

// ---------------- CSR aggregate ----------------

__global__ void __launch_bounds__(256) k_aggregate(
    const int* __restrict__ rowptr, const int* __restrict__ srow,
    const float* __restrict__ snorm, const float* __restrict__ dinv,
    const float* __restrict__ bias, const __half* __restrict__ t16,
    __nv_bfloat16* __restrict__ hhi, __nv_bfloat16* __restrict__ hlo,
    int n, int doRelu)
{
    int node = blockIdx.x * 8 + (threadIdx.x >> 5);
    if (node >= n) return;
    const int lane = threadIdx.x & 31;
    const int f4 = lane * 4;

    float d = __ldg(dinv + node);
    float d2 = d * d;

    uint2 sraw = *reinterpret_cast<const uint2*>(t16 + (size_t)node * FDIM + f4);
    float2 s0 = __half22float2(*reinterpret_cast<__half2*>(&sraw.x));
    float2 s1 = __half22float2(*reinterpret_cast<__half2*>(&sraw.y));
    float4 bv = *reinterpret_cast<const float4*>(bias + f4);
    float4 acc;
    acc.x = fmaf(s0.x, d2, bv.x);
    acc.y = fmaf(s0.y, d2, bv.y);
    acc.z = fmaf(s1.x, d2, bv.z);
    acc.w = fmaf(s1.y, d2, bv.w);

    int j = __ldg(rowptr + node);
    const int jend = __ldg(rowptr + node + 1);

#define GATHER(rj, wj)                                                          \
    do {                                                                        \
        uint2 raw = *reinterpret_cast<const uint2*>(t16 + (size_t)(rj) * FDIM + f4); \
        float2 p0 = __half22float2(*reinterpret_cast<__half2*>(&raw.x));        \
        float2 p1 = __half22float2(*reinterpret_cast<__half2*>(&raw.y));        \
        acc.x = fmaf(p0.x, (wj), acc.x); acc.y = fmaf(p0.y, (wj), acc.y);       \
        acc.z = fmaf(p1.x, (wj), acc.z); acc.w = fmaf(p1.y, (wj), acc.w);       \
    } while (0)

    for (; j + 3 < jend; j += 4) {
        int r0 = __ldg(srow + j);
        int r1 = __ldg(srow + j + 1);
        int r2 = __ldg(srow + j + 2);
        int r3 = __ldg(srow + j + 3);
        float w0 = __ldg(snorm + j);
        float w1 = __ldg(snorm + j + 1);
        float w2 = __ldg(snorm + j + 2);
        float w3 = __ldg(snorm + j + 3);
        GATHER(r0, w0);
        GATHER(r1, w1);
        GATHER(r2, w2);
        GATHER(r3, w3);
    }
    for (; j < jend; j++) {
        int r0 = __ldg(srow + j);
        float w0 = __ldg(snorm + j);
        GATHER(r0, w0);
    }
#undef GATHER

    if (doRelu) {
        acc.x = fmaxf(acc.x, 0.f); acc.y = fmaxf(acc.y, 0.f);
        acc.z = fmaxf(acc.z, 0.f); acc.w = fmaxf(acc.w, 0.f);
    }
    uint32_t h01 = bfpack(acc.x, acc.y);
    uint32_t h23 = bfpack(acc.z, acc.w);
    uint32_t l01 = bfpack(acc.x - bflo(h01), acc.y - bfhi(h01));
    uint32_t l23 = bfpack(acc.z - bflo(h23), acc.w - bfhi(h23));
    const size_t o = (size_t)node * FDIM + f4;
    *reinterpret_cast<uint2*>(hhi + o) = make_uint2(h01, h23);
    *reinterpret_cast<uint2*>(hlo + o) = make_uint2(l01, l23);
}

// ---------------- launch ----------------

extern "C" void kernel_launch(void* const* d_in, const int* in_sizes, int n_in,
                              void* d_out, int out_size) {
    const float* x    = (const float*)d_in[0];
    const int*   ei   = (const int*)  d_in[1];
    const float* ew   = (const float*)d_in[2];
    const float* Wc[4] = {(const float*)d_in[3], (const float*)d_in[5],
                          (const float*)d_in[7], (const float*)d_in[9]};
    const float* bc[4] = {(const float*)d_in[4], (const float*)d_in[6],
                          (const float*)d_in[8], (const float*)d_in[10]};
    const float* Wout = (const float*)d_in[11];
    const float* bout = (const float*)d_in[12];
    float* out = (float*)d_out;

    const int N = in_sizes[0] / FDIM;
    const int E = in_sizes[2];
    const int* rowp = ei;
    const int* colp = ei + E;

    float *deg, *dinv, *snorm;
    int *cnt, *rowptr, *cur, *srow, *bsum, *boffs;
    __half* t16;
    __nv_bfloat16 *whi, *wlo, *hhi, *hlo, *xhi, *xlo;
    cudaGetSymbolAddress((void**)&t16, g_t16);
    cudaGetSymbolAddress((void**)&deg, g_deg);
    cudaGetSymbolAddress((void**)&dinv, g_dinv);
    cudaGetSymbolAddress((void**)&cnt, g_cnt);
    cudaGetSymbolAddress((void**)&rowptr, g_rowptr);
    cudaGetSymbolAddress((void**)&cur, g_cursor);
    cudaGetSymbolAddress((void**)&srow, g_srow);
    cudaGetSymbolAddress((void**)&snorm, g_snorm);
    cudaGetSymbolAddress((void**)&bsum, g_bsum);
    cudaGetSymbolAddress((void**)&boffs, g_boffs);
    cudaGetSymbolAddress((void**)&whi, g_whi);
    cudaGetSymbolAddress((void**)&wlo, g_wlo);
    cudaGetSymbolAddress((void**)&hhi, g_hhi);
    cudaGetSymbolAddress((void**)&hlo, g_hlo);
    cudaGetSymbolAddress((void**)&xhi, g_xhi);
    cudaGetSymbolAddress((void**)&xlo, g_xlo);

    static const int SMEM_DYN = 98304;
    cudaFuncSetAttribute(k_gemm_mma, cudaFuncAttributeMaxDynamicSharedMemorySize, SMEM_DYN);

    // Side stream + fork/join events (host-side resources only, created once;
    // work per call is identical — no device allocation).
    static cudaStream_t s2 = nullptr;
    static cudaEvent_t eFork = nullptr, eJoin = nullptr;
    if (s2 == nullptr) {
        cudaStreamCreateWithFlags(&s2, cudaStreamNonBlocking);
        cudaEventCreateWithFlags(&eFork, cudaEventDisableTiming);
        cudaEventCreateWithFlags(&eJoin, cudaEventDisableTiming);
    }

    const int TB = 256;
    const int nScanBlk = (N + SCAN_B - 1) / SCAN_B;
    const int wpBlocks = (16384 + TB - 1) / TB;
    const int gemmBlocks = (N + BM - 1) / BM;
    const int aggBlocks  = (N + 7) / 8;
    const int xpBlocks   = (N * 32 + TB - 1) / TB;

    // ---- main stream: GEMM-0 chain ----
    k_wprep<<<wpBlocks, TB>>>(Wc[0], whi, wlo);                                // #1
    k_xprep<<<xpBlocks, TB>>>(x, xhi, xlo, N * 32);                            // #2

    // fork side stream from capture origin
    cudaEventRecord(eFork, 0);
    cudaStreamWaitEvent(s2, eFork, 0);

    k_init<<<(N + TB - 1) / TB, TB, 0, s2>>>(deg, cnt, cur, N);                // #3
    k_gemm_mma<<<gemmBlocks, TB, SMEM_DYN>>>(xhi, xlo, whi, wlo,
                                             nullptr, t16, nullptr, N, 0);     // #4 <- profiled
    // ---- side stream: CSR build chain (overlaps gemm0) ----
    k_deg_hist<<<(E + TB - 1) / TB, TB, 0, s2>>>(colp, ew, deg, cnt, E);
    k_dinv<<<(N + TB - 1) / TB, TB, 0, s2>>>(deg, dinv, N);
    k_scan_local<<<nScanBlk, SCAN_B, 0, s2>>>(cnt, rowptr, bsum, N);
    k_scan_mid<<<1, MAXBLK, 0, s2>>>(bsum, boffs, nScanBlk);
    k_scan_add<<<nScanBlk, SCAN_B, 0, s2>>>(rowptr, boffs, N, E);
    k_fill<<<(E + TB - 1) / TB, TB, 0, s2>>>(rowp, colp, ew, dinv, rowptr,
                                             cur, srow, snorm, E);
    {
        dim3 wg(wpBlocks, 4);
        k_wprep4<<<wg, TB, 0, s2>>>(Wc[1], Wc[2], Wc[3], Wout, whi, wlo);
    }
    cudaEventRecord(eJoin, s2);
    cudaStreamWaitEvent(0, eJoin, 0);

    // ---- layers (main stream, serial chain) ----
    k_aggregate<<<aggBlocks, TB>>>(rowptr, srow, snorm, dinv, bc[0], t16,
                                   hhi, hlo, N, 1);
    for (int l = 1; l < 4; l++) {
        k_gemm_mma<<<gemmBlocks, TB, SMEM_DYN>>>(hhi, hlo,
                                                 whi + l * 16384, wlo + l * 16384,
                                                 nullptr, t16, nullptr, N, 0);
        k_aggregate<<<aggBlocks, TB>>>(rowptr, srow, snorm, dinv, bc[l], t16,
                                       hhi, hlo, N, (l < 3) ? 1 : 0);
    }

    k_gemm_mma<<<gemmBlocks, TB, SMEM_DYN>>>(hhi, hlo,
                                             whi + 4 * 16384, wlo + 4 * 16384,
                                             bout, nullptr, out, N, 1);
}

// round 13
// speedup vs baseline: 2.0615x; 1.1024x over previous
#include <cuda_runtime.h>
#include <cuda_bf16.h>
#include <cuda_fp16.h>
#include <cstdint>

// ---------------------------------------------------------------------------
// GCN: 4x GCNConv(128->128) + output linear(128->128), N=100000, E=1600000.
// Round 13: 2-term fp16 GEMM (A fp16, W = fp16 hi+lo): 16 mma/k-step (was
// 24), 6 ldsm (was 8); aggregate writes single fp16 array (was split bf16).
// ---------------------------------------------------------------------------

#define NMAX 100096
#define EMAX 1600000
#define FDIM 128
#define SCAN_B 1024
#define MAXBLK 128
#define BM 64

__device__ __align__(16) __half g_t16[(size_t)NMAX * FDIM];   // conv GEMM out
__device__ __align__(16) __half g_h16[(size_t)NMAX * FDIM];   // aggregate out
__device__ __align__(16) __half g_x16[(size_t)NMAX * FDIM];   // fp16 input x
__device__ float g_deg[NMAX];
__device__ float g_dinv[NMAX];
__device__ int   g_cnt[NMAX];
__device__ int   g_rowptr[NMAX + 1];
__device__ int   g_cursor[NMAX];
__device__ int   g_srow[EMAX];
__device__ float g_snorm[EMAX];
__device__ int   g_bsum[MAXBLK];
__device__ int   g_boffs[MAXBLK];
__device__ __align__(16) __half g_whi[5 * 16384];
__device__ __align__(16) __half g_wlo[5 * 16384];

// ---------------- helpers ----------------

__device__ __forceinline__ uint32_t smem_u32(const void* p) {
    uint32_t a;
    asm("{ .reg .u64 t; cvta.to.shared.u64 t, %1; cvt.u32.u64 %0, t; }" : "=r"(a) : "l"(p));
    return a;
}

__device__ __forceinline__ void ldsm4(uint32_t& r0, uint32_t& r1, uint32_t& r2,
                                      uint32_t& r3, uint32_t addr) {
    asm volatile("ldmatrix.sync.aligned.m8n8.x4.shared.b16 {%0,%1,%2,%3}, [%4];"
                 : "=r"(r0), "=r"(r1), "=r"(r2), "=r"(r3) : "r"(addr));
}

__device__ __forceinline__ void mma16816h(float* c, const uint32_t* a,
                                          uint32_t b0, uint32_t b1) {
    asm volatile(
        "mma.sync.aligned.m16n8k16.row.col.f32.f16.f16.f32 "
        "{%0,%1,%2,%3}, {%4,%5,%6,%7}, {%8,%9}, {%0,%1,%2,%3};"
        : "+f"(c[0]), "+f"(c[1]), "+f"(c[2]), "+f"(c[3])
        : "r"(a[0]), "r"(a[1]), "r"(a[2]), "r"(a[3]), "r"(b0), "r"(b1));
}

__device__ __forceinline__ void cp16(uint32_t dst, const void* src) {
    asm volatile("cp.async.ca.shared.global [%0], [%1], 16;" :: "r"(dst), "l"(src));
}

__device__ __forceinline__ uint32_t swz(int r, int k) {
    return (uint32_t)((r << 8) + ((((k >> 3) ^ (r & 7)) << 4)) + ((k & 7) << 1));
}

// ---------------- x prep: fp32 -> fp16 ----------------

__global__ void k_xprep(const float* __restrict__ x, __half* __restrict__ x16,
                        int total4) {
    int i = blockIdx.x * blockDim.x + threadIdx.x;
    if (i >= total4) return;
    float4 v = reinterpret_cast<const float4*>(x)[i];
    __half2 p0 = __floats2half2_rn(v.x, v.y);
    __half2 p1 = __floats2half2_rn(v.z, v.w);
    uint2 o;
    o.x = *reinterpret_cast<uint32_t*>(&p0);
    o.y = *reinterpret_cast<uint32_t*>(&p1);
    reinterpret_cast<uint2*>(x16)[i] = o;
}

// ---------------- degree + histogram ----------------

__global__ void k_init(float* __restrict__ deg, int* __restrict__ cnt,
                       int* __restrict__ cur, int n) {
    int i = blockIdx.x * blockDim.x + threadIdx.x;
    if (i < n) { deg[i] = 1.0f; cnt[i] = 0; cur[i] = 0; }
}

__global__ void k_deg_hist(const int* __restrict__ col, const float* __restrict__ ew,
                           float* __restrict__ deg, int* __restrict__ cnt, int E) {
    int e = blockIdx.x * blockDim.x + threadIdx.x;
    if (e < E) {
        int c = col[e];
        atomicAdd(&deg[c], ew[e]);
        atomicAdd(&cnt[c], 1);
    }
}

__global__ void k_dinv(const float* __restrict__ deg, float* __restrict__ dinv, int n) {
    int i = blockIdx.x * blockDim.x + threadIdx.x;
    if (i < n) {
        float d = deg[i];
        dinv[i] = (d > 0.0f) ? rsqrtf(d) : 0.0f;
    }
}

// ---------------- 3-phase scan ----------------

__global__ void __launch_bounds__(SCAN_B) k_scan_local(
    const int* __restrict__ cnt, int* __restrict__ rowptr,
    int* __restrict__ bsum, int n)
{
    __shared__ int s[SCAN_B];
    const int tid = threadIdx.x;
    const int i = blockIdx.x * SCAN_B + tid;
    int v = (i < n) ? cnt[i] : 0;
    s[tid] = v;
    __syncthreads();
#pragma unroll
    for (int ofs = 1; ofs < SCAN_B; ofs <<= 1) {
        int t = (tid >= ofs) ? s[tid - ofs] : 0;
        __syncthreads();
        s[tid] += t;
        __syncthreads();
    }
    if (i < n) rowptr[i] = s[tid] - v;
    if (tid == SCAN_B - 1) bsum[blockIdx.x] = s[tid];
}

__global__ void __launch_bounds__(MAXBLK) k_scan_mid(
    const int* __restrict__ bsum, int* __restrict__ boffs, int nb)
{
    __shared__ int s[MAXBLK];
    const int tid = threadIdx.x;
    int v = (tid < nb) ? bsum[tid] : 0;
    s[tid] = v;
    __syncthreads();
#pragma unroll
    for (int ofs = 1; ofs < MAXBLK; ofs <<= 1) {
        int t = (tid >= ofs) ? s[tid - ofs] : 0;
        __syncthreads();
        s[tid] += t;
        __syncthreads();
    }
    if (tid < nb) boffs[tid] = s[tid] - v;
}

__global__ void __launch_bounds__(SCAN_B) k_scan_add(
    int* __restrict__ rowptr, const int* __restrict__ boffs, int n, int E)
{
    const int i = blockIdx.x * SCAN_B + threadIdx.x;
    if (i < n) rowptr[i] += boffs[blockIdx.x];
    if (i == 0) rowptr[n] = E;
}

// ---------------- counting-sort fill ----------------

__global__ void k_fill(const int* __restrict__ row, const int* __restrict__ col,
                       const float* __restrict__ ew, const float* __restrict__ dinv,
                       const int* __restrict__ rowptr, int* __restrict__ cur,
                       int* __restrict__ srow, float* __restrict__ snorm, int E) {
    int e = blockIdx.x * blockDim.x + threadIdx.x;
    if (e >= E) return;
    int r = row[e];
    int c = col[e];
    int pos = rowptr[c] + atomicAdd(&cur[c], 1);
    srow[pos] = r;
    snorm[pos] = dinv[r] * ew[e] * dinv[c];
}

// ---------------- weight prep: fp16 hi/lo ----------------

__device__ __forceinline__ void wprep_one(const float* W, __half* dhi,
                                          __half* dlo, int idx) {
    int n = idx >> 7, k = idx & 127;
    float w = W[k * 128 + n];                 // B[n][k] = W[k][n]
    __half hi = __float2half_rn(w);
    __half lo = __float2half_rn(w - __half2float(hi));
    dhi[n * 128 + k] = hi;
    dlo[n * 128 + k] = lo;
}

__global__ void k_wprep(const float* __restrict__ W, __half* __restrict__ dhi,
                        __half* __restrict__ dlo) {
    int idx = blockIdx.x * blockDim.x + threadIdx.x;
    if (idx >= 16384) return;
    wprep_one(W, dhi, dlo, idx);
}

__global__ void k_wprep4(const float* __restrict__ W1, const float* __restrict__ W2,
                         const float* __restrict__ W3, const float* __restrict__ W4,
                         __half* __restrict__ hbase, __half* __restrict__ lbase) {
    int idx = blockIdx.x * blockDim.x + threadIdx.x;
    if (idx >= 16384) return;
    const float* W = (blockIdx.y == 0) ? W1 : (blockIdx.y == 1) ? W2
                   : (blockIdx.y == 2) ? W3 : W4;
    int ofs = (blockIdx.y + 1) * 16384;
    wprep_one(W, hbase + ofs, lbase + ofs, idx);
}

// ---------------- fp16 HMMA GEMM: C = A @ (Whi + Wlo) ----------------
// A fp16 (16KB smem), W fp16 hi/lo (64KB). 2 terms, 16 mma / 6 ldsm per k-step.

__global__ void __launch_bounds__(256, 2) k_gemm_mma(
    const __half* __restrict__ A,
    const __half* __restrict__ whi, const __half* __restrict__ wlo,
    const float* __restrict__ bias, __half* __restrict__ Ch,
    float* __restrict__ Cf, int M, int outFloat)
{
    extern __shared__ char sm[];
    char* sA   = sm;                  // 16KB
    char* sWhi = sm + 16384;          // 32KB
    char* sWlo = sm + 49152;          // 32KB

    const int tid = threadIdx.x;
    const int wid = tid >> 5;
    const int lane = tid & 31;
    const int rbase = blockIdx.x * BM;

    const uint32_t uA   = smem_u32(sA);
    const uint32_t uWhi = smem_u32(sWhi);
    const uint32_t uWlo = smem_u32(sWlo);

    for (int i = tid; i < 2048; i += 256) {
        int r = i >> 4, c = i & 15;
        uint32_t doff = (uint32_t)((r << 8) + ((c ^ (r & 7)) << 4));
        cp16(uWhi + doff, whi + r * 128 + c * 8);
        cp16(uWlo + doff, wlo + r * 128 + c * 8);
    }
    for (int i = tid; i < 1024; i += 256) {
        int r = i >> 4, c = i & 15;
        int grow = rbase + r;
        if (grow < M) {
            uint32_t doff = (uint32_t)((r << 8) + ((c ^ (r & 7)) << 4));
            cp16(uA + doff, A + (size_t)grow * FDIM + c * 8);
        }
    }
    asm volatile("cp.async.commit_group;" ::: "memory");
    asm volatile("cp.async.wait_group 0;" ::: "memory");
    __syncthreads();

    const int warpRow = (wid & 1) * 32;
    const int warpCol = (wid >> 1) * 32;
    const int a_r = lane & 15;
    const int a_k = (lane >> 4) << 3;
    const int b_n = (lane & 7) + ((lane >> 4) << 3);
    const int b_k = ((lane >> 3) & 1) << 3;

    float c[2][4][4];
#pragma unroll
    for (int mi = 0; mi < 2; mi++)
#pragma unroll
        for (int ni = 0; ni < 4; ni++)
#pragma unroll
            for (int q = 0; q < 4; q++) c[mi][ni][q] = 0.0f;

    uint32_t a0[2][4], a1[2][4];
    uint32_t bh0[2][4], bh1[2][4], bl0[2][4], bl1[2][4];

#define LOADK(buf, k0)                                                          \
    do {                                                                        \
        ldsm4(a0[buf][0], a0[buf][1], a0[buf][2], a0[buf][3],                   \
              uA + swz(warpRow + a_r,      (k0) + a_k));                        \
        ldsm4(a1[buf][0], a1[buf][1], a1[buf][2], a1[buf][3],                   \
              uA + swz(warpRow + 16 + a_r, (k0) + a_k));                        \
        ldsm4(bh0[buf][0], bh0[buf][1], bh0[buf][2], bh0[buf][3],               \
              uWhi + swz(warpCol + b_n,      (k0) + b_k));                      \
        ldsm4(bh1[buf][0], bh1[buf][1], bh1[buf][2], bh1[buf][3],               \
              uWhi + swz(warpCol + 16 + b_n, (k0) + b_k));                      \
        ldsm4(bl0[buf][0], bl0[buf][1], bl0[buf][2], bl0[buf][3],               \
              uWlo + swz(warpCol + b_n,      (k0) + b_k));                      \
        ldsm4(bl1[buf][0], bl1[buf][1], bl1[buf][2], bl1[buf][3],               \
              uWlo + swz(warpCol + 16 + b_n, (k0) + b_k));                      \
    } while (0)

    LOADK(0, 0);
#pragma unroll
    for (int it = 0; it < 8; it++) {
        const int cur = it & 1, nxt = cur ^ 1;
        if (it < 7) LOADK(nxt, (it + 1) << 4);
        // term0: A * Whi
        mma16816h(c[0][0], a0[cur], bh0[cur][0], bh0[cur][1]);
        mma16816h(c[0][1], a0[cur], bh0[cur][2], bh0[cur][3]);
        mma16816h(c[0][2], a0[cur], bh1[cur][0], bh1[cur][1]);
        mma16816h(c[0][3], a0[cur], bh1[cur][2], bh1[cur][3]);
        mma16816h(c[1][0], a1[cur], bh0[cur][0], bh0[cur][1]);
        mma16816h(c[1][1], a1[cur], bh0[cur][2], bh0[cur][3]);
        mma16816h(c[1][2], a1[cur], bh1[cur][0], bh1[cur][1]);
        mma16816h(c[1][3], a1[cur], bh1[cur][2], bh1[cur][3]);
        // term1: A * Wlo
        mma16816h(c[0][0], a0[cur], bl0[cur][0], bl0[cur][1]);
        mma16816h(c[0][1], a0[cur], bl0[cur][2], bl0[cur][3]);
        mma16816h(c[0][2], a0[cur], bl1[cur][0], bl1[cur][1]);
        mma16816h(c[0][3], a0[cur], bl1[cur][2], bl1[cur][3]);
        mma16816h(c[1][0], a1[cur], bl0[cur][0], bl0[cur][1]);
        mma16816h(c[1][1], a1[cur], bl0[cur][2], bl0[cur][3]);
        mma16816h(c[1][2], a1[cur], bl1[cur][0], bl1[cur][1]);
        mma16816h(c[1][3], a1[cur], bl1[cur][2], bl1[cur][3]);
    }
#undef LOADK

    const int crow = lane >> 2;
    const int ccol = (lane & 3) * 2;
#pragma unroll
    for (int mi = 0; mi < 2; mi++) {
#pragma unroll
        for (int ni = 0; ni < 4; ni++) {
            int colg = warpCol + ni * 8 + ccol;
            int r0 = rbase + warpRow + mi * 16 + crow;
            int r1 = r0 + 8;
            if (outFloat) {
                float bx = bias[colg], by = bias[colg + 1];
                if (r0 < M) {
                    float2 v = make_float2(c[mi][ni][0] + bx, c[mi][ni][1] + by);
                    *reinterpret_cast<float2*>(Cf + (size_t)r0 * FDIM + colg) = v;
                }
                if (r1 < M) {
                    float2 v = make_float2(c[mi][ni][2] + bx, c[mi][ni][3] + by);
                    *reinterpret_cast<float2*>(Cf + (size_t)r1 * FDIM + colg) = v;
                }
            } else {
                if (r0 < M) {
                    __half2 v = __floats2half2_rn(c[mi][ni][0], c[mi][ni][1]);
                    *reinterpret_cast<__half2*>(Ch + (size_t)r0 * FDIM + colg) = v;
                }
                if (r1 < M) {
                    __half2 v = __floats2half2_rn(c[mi][ni][2], c[mi][ni][3]);
                    *reinterpret_cast<__half2*>(Ch + (size_t)r1 * FDIM + colg) = v;
                }
            }
        }
    }
}

// ---------------- CSR aggregate: fp16 gathers -> fp16 out ----------------

__global__ void __launch_bounds__(256) k_aggregate(
    const int* __restrict__ rowptr, const int* __restrict__ srow,
    const float* __restrict__ snorm, const float* __restrict__ dinv,
    const float* __restrict__ bias, const __half* __restrict__ t16,
    __half* __restrict__ h16, int n, int doRelu)
{
    int node = blockIdx.x * 8 + (threadIdx.x >> 5);
    if (node >= n) return;
    const int lane = threadIdx.x & 31;
    const int f4 = lane * 4;

    float d = __ldg(dinv + node);
    float d2 = d * d;

    uint2 sraw = *reinterpret_cast<const uint2*>(t16 + (size_t)node * FDIM + f4);
    float2 s0 = __half22float2(*reinterpret_cast<__half2*>(&sraw.x));
    float2 s1 = __half22float2(*reinterpret_cast<__half2*>(&sraw.y));
    float4 bv = *reinterpret_cast<const float4*>(bias + f4);
    float4 acc;
    acc.x = fmaf(s0.x, d2, bv.x);
    acc.y = fmaf(s0.y, d2, bv.y);
    acc.z = fmaf(s1.x, d2, bv.z);
    acc.w = fmaf(s1.y, d2, bv.w);

    int j = __ldg(rowptr + node);
    const int jend = __ldg(rowptr + node + 1);

#define GATHER(rj, wj)                                                          \
    do {                                                                        \
        uint2 raw = *reinterpret_cast<const uint2*>(t16 + (size_t)(rj) * FDIM + f4); \
        float2 p0 = __half22float2(*reinterpret_cast<__half2*>(&raw.x));        \
        float2 p1 = __half22float2(*reinterpret_cast<__half2*>(&raw.y));        \
        acc.x = fmaf(p0.x, (wj), acc.x); acc.y = fmaf(p0.y, (wj), acc.y);       \
        acc.z = fmaf(p1.x, (wj), acc.z); acc.w = fmaf(p1.y, (wj), acc.w);       \
    } while (0)

    for (; j + 3 < jend; j += 4) {
        int r0 = __ldg(srow + j);
        int r1 = __ldg(srow + j + 1);
        int r2 = __ldg(srow + j + 2);
        int r3 = __ldg(srow + j + 3);
        float w0 = __ldg(snorm + j);
        float w1 = __ldg(snorm + j + 1);
        float w2 = __ldg(snorm + j + 2);
        float w3 = __ldg(snorm + j + 3);
        GATHER(r0, w0);
        GATHER(r1, w1);
        GATHER(r2, w2);
        GATHER(r3, w3);
    }
    for (; j < jend; j++) {
        int r0 = __ldg(srow + j);
        float w0 = __ldg(snorm + j);
        GATHER(r0, w0);
    }
#undef GATHER

    if (doRelu) {
        acc.x = fmaxf(acc.x, 0.f); acc.y = fmaxf(acc.y, 0.f);
        acc.z = fmaxf(acc.z, 0.f); acc.w = fmaxf(acc.w, 0.f);
    }
    __half2 o0 = __floats2half2_rn(acc.x, acc.y);
    __half2 o1 = __floats2half2_rn(acc.z, acc.w);
    uint2 o;
    o.x = *reinterpret_cast<uint32_t*>(&o0);
    o.y = *reinterpret_cast<uint32_t*>(&o1);
    *reinterpret_cast<uint2*>(h16 + (size_t)node * FDIM + f4) = o;
}

// ---------------- launch ----------------

extern "C" void kernel_launch(void* const* d_in, const int* in_sizes, int n_in,
                              void* d_out, int out_size) {
    const float* x    = (const float*)d_in[0];
    const int*   ei   = (const int*)  d_in[1];
    const float* ew   = (const float*)d_in[2];
    const float* Wc[4] = {(const float*)d_in[3], (const float*)d_in[5],
                          (const float*)d_in[7], (const float*)d_in[9]};
    const float* bc[4] = {(const float*)d_in[4], (const float*)d_in[6],
                          (const float*)d_in[8], (const float*)d_in[10]};
    const float* Wout = (const float*)d_in[11];
    const float* bout = (const float*)d_in[12];
    float* out = (float*)d_out;

    const int N = in_sizes[0] / FDIM;
    const int E = in_sizes[2];
    const int* rowp = ei;
    const int* colp = ei + E;

    float *deg, *dinv, *snorm;
    int *cnt, *rowptr, *cur, *srow, *bsum, *boffs;
    __half *t16, *h16, *x16, *whi, *wlo;
    cudaGetSymbolAddress((void**)&t16, g_t16);
    cudaGetSymbolAddress((void**)&h16, g_h16);
    cudaGetSymbolAddress((void**)&x16, g_x16);
    cudaGetSymbolAddress((void**)&deg, g_deg);
    cudaGetSymbolAddress((void**)&dinv, g_dinv);
    cudaGetSymbolAddress((void**)&cnt, g_cnt);
    cudaGetSymbolAddress((void**)&rowptr, g_rowptr);
    cudaGetSymbolAddress((void**)&cur, g_cursor);
    cudaGetSymbolAddress((void**)&srow, g_srow);
    cudaGetSymbolAddress((void**)&snorm, g_snorm);
    cudaGetSymbolAddress((void**)&bsum, g_bsum);
    cudaGetSymbolAddress((void**)&boffs, g_boffs);
    cudaGetSymbolAddress((void**)&whi, g_whi);
    cudaGetSymbolAddress((void**)&wlo, g_wlo);

    static const int SMEM_DYN = 81920;
    cudaFuncSetAttribute(k_gemm_mma, cudaFuncAttributeMaxDynamicSharedMemorySize, SMEM_DYN);

    static cudaStream_t s2 = nullptr;
    static cudaEvent_t eFork = nullptr, eJoin = nullptr;
    if (s2 == nullptr) {
        cudaStreamCreateWithFlags(&s2, cudaStreamNonBlocking);
        cudaEventCreateWithFlags(&eFork, cudaEventDisableTiming);
        cudaEventCreateWithFlags(&eJoin, cudaEventDisableTiming);
    }

    const int TB = 256;
    const int nScanBlk = (N + SCAN_B - 1) / SCAN_B;
    const int wpBlocks = (16384 + TB - 1) / TB;
    const int gemmBlocks = (N + BM - 1) / BM;
    const int aggBlocks  = (N + 7) / 8;
    const int xpBlocks   = (N * 32 + TB - 1) / TB;

    // ---- main stream: GEMM-0 chain (gemm is launch #4 for ncu) ----
    k_wprep<<<wpBlocks, TB>>>(Wc[0], whi, wlo);                                // #1
    k_xprep<<<xpBlocks, TB>>>(x, x16, N * 32);                                 // #2

    cudaEventRecord(eFork, 0);
    cudaStreamWaitEvent(s2, eFork, 0);

    k_init<<<(N + TB - 1) / TB, TB, 0, s2>>>(deg, cnt, cur, N);                // #3
    k_gemm_mma<<<gemmBlocks, TB, SMEM_DYN>>>(x16, whi, wlo,
                                             nullptr, t16, nullptr, N, 0);     // #4 <- profiled
    // ---- side stream: CSR build chain ----
    k_deg_hist<<<(E + TB - 1) / TB, TB, 0, s2>>>(colp, ew, deg, cnt, E);
    k_dinv<<<(N + TB - 1) / TB, TB, 0, s2>>>(deg, dinv, N);
    k_scan_local<<<nScanBlk, SCAN_B, 0, s2>>>(cnt, rowptr, bsum, N);
    k_scan_mid<<<1, MAXBLK, 0, s2>>>(bsum, boffs, nScanBlk);
    k_scan_add<<<nScanBlk, SCAN_B, 0, s2>>>(rowptr, boffs, N, E);
    k_fill<<<(E + TB - 1) / TB, TB, 0, s2>>>(rowp, colp, ew, dinv, rowptr,
                                             cur, srow, snorm, E);
    {
        dim3 wg(wpBlocks, 4);
        k_wprep4<<<wg, TB, 0, s2>>>(Wc[1], Wc[2], Wc[3], Wout, whi, wlo);
    }
    cudaEventRecord(eJoin, s2);
    cudaStreamWaitEvent(0, eJoin, 0);

    // ---- layers ----
    k_aggregate<<<aggBlocks, TB>>>(rowptr, srow, snorm, dinv, bc[0], t16,
                                   h16, N, 1);
    for (int l = 1; l < 4; l++) {
        k_gemm_mma<<<gemmBlocks, TB, SMEM_DYN>>>(h16,
                                                 whi + l * 16384, wlo + l * 16384,
                                                 nullptr, t16, nullptr, N, 0);
        k_aggregate<<<aggBlocks, TB>>>(rowptr, srow, snorm, dinv, bc[l], t16,
                                       h16, N, (l < 3) ? 1 : 0);
    }

    k_gemm_mma<<<gemmBlocks, TB, SMEM_DYN>>>(h16,
                                             whi + 4 * 16384, wlo + 4 * 16384,
                                             bout, nullptr, out, N, 1);
}

// round 14
// speedup vs baseline: 2.2909x; 1.1112x over previous
#include <cuda_runtime.h>
#include <cuda_bf16.h>
#include <cuda_fp16.h>
#include <cstdint>

// ---------------------------------------------------------------------------
// GCN: 4x GCNConv(128->128) + output linear(128->128), N=100000, E=1600000.
// Round 14: 1-term pure-fp16 GEMM (W single fp16): 8 mma / 4 ldsm per k-step
// (was 16/6), smem 48KB -> 3 CTAs/SM. Error budget allows one more fp16
// surface (measured ~2e-4 per quant surface; margin stays >3x).
// ---------------------------------------------------------------------------

#define NMAX 100096
#define EMAX 1600000
#define FDIM 128
#define SCAN_B 1024
#define MAXBLK 128
#define BM 64

__device__ __align__(16) __half g_t16[(size_t)NMAX * FDIM];   // conv GEMM out
__device__ __align__(16) __half g_h16[(size_t)NMAX * FDIM];   // aggregate out
__device__ __align__(16) __half g_x16[(size_t)NMAX * FDIM];   // fp16 input x
__device__ float g_deg[NMAX];
__device__ float g_dinv[NMAX];
__device__ int   g_cnt[NMAX];
__device__ int   g_rowptr[NMAX + 1];
__device__ int   g_cursor[NMAX];
__device__ int   g_srow[EMAX];
__device__ float g_snorm[EMAX];
__device__ int   g_bsum[MAXBLK];
__device__ int   g_boffs[MAXBLK];
__device__ __align__(16) __half g_w16[5 * 16384];

// ---------------- helpers ----------------

__device__ __forceinline__ uint32_t smem_u32(const void* p) {
    uint32_t a;
    asm("{ .reg .u64 t; cvta.to.shared.u64 t, %1; cvt.u32.u64 %0, t; }" : "=r"(a) : "l"(p));
    return a;
}

__device__ __forceinline__ void ldsm4(uint32_t& r0, uint32_t& r1, uint32_t& r2,
                                      uint32_t& r3, uint32_t addr) {
    asm volatile("ldmatrix.sync.aligned.m8n8.x4.shared.b16 {%0,%1,%2,%3}, [%4];"
                 : "=r"(r0), "=r"(r1), "=r"(r2), "=r"(r3) : "r"(addr));
}

__device__ __forceinline__ void mma16816h(float* c, const uint32_t* a,
                                          uint32_t b0, uint32_t b1) {
    asm volatile(
        "mma.sync.aligned.m16n8k16.row.col.f32.f16.f16.f32 "
        "{%0,%1,%2,%3}, {%4,%5,%6,%7}, {%8,%9}, {%0,%1,%2,%3};"
        : "+f"(c[0]), "+f"(c[1]), "+f"(c[2]), "+f"(c[3])
        : "r"(a[0]), "r"(a[1]), "r"(a[2]), "r"(a[3]), "r"(b0), "r"(b1));
}

__device__ __forceinline__ void cp16(uint32_t dst, const void* src) {
    asm volatile("cp.async.ca.shared.global [%0], [%1], 16;" :: "r"(dst), "l"(src));
}

__device__ __forceinline__ uint32_t swz(int r, int k) {
    return (uint32_t)((r << 8) + ((((k >> 3) ^ (r & 7)) << 4)) + ((k & 7) << 1));
}

// ---------------- x prep: fp32 -> fp16 ----------------

__global__ void k_xprep(const float* __restrict__ x, __half* __restrict__ x16,
                        int total4) {
    int i = blockIdx.x * blockDim.x + threadIdx.x;
    if (i >= total4) return;
    float4 v = reinterpret_cast<const float4*>(x)[i];
    __half2 p0 = __floats2half2_rn(v.x, v.y);
    __half2 p1 = __floats2half2_rn(v.z, v.w);
    uint2 o;
    o.x = *reinterpret_cast<uint32_t*>(&p0);
    o.y = *reinterpret_cast<uint32_t*>(&p1);
    reinterpret_cast<uint2*>(x16)[i] = o;
}

// ---------------- degree + histogram ----------------

__global__ void k_init(float* __restrict__ deg, int* __restrict__ cnt,
                       int* __restrict__ cur, int n) {
    int i = blockIdx.x * blockDim.x + threadIdx.x;
    if (i < n) { deg[i] = 1.0f; cnt[i] = 0; cur[i] = 0; }
}

__global__ void k_deg_hist(const int* __restrict__ col, const float* __restrict__ ew,
                           float* __restrict__ deg, int* __restrict__ cnt, int E) {
    int e = blockIdx.x * blockDim.x + threadIdx.x;
    if (e < E) {
        int c = col[e];
        atomicAdd(&deg[c], ew[e]);
        atomicAdd(&cnt[c], 1);
    }
}

__global__ void k_dinv(const float* __restrict__ deg, float* __restrict__ dinv, int n) {
    int i = blockIdx.x * blockDim.x + threadIdx.x;
    if (i < n) {
        float d = deg[i];
        dinv[i] = (d > 0.0f) ? rsqrtf(d) : 0.0f;
    }
}

// ---------------- 3-phase scan ----------------

__global__ void __launch_bounds__(SCAN_B) k_scan_local(
    const int* __restrict__ cnt, int* __restrict__ rowptr,
    int* __restrict__ bsum, int n)
{
    __shared__ int s[SCAN_B];
    const int tid = threadIdx.x;
    const int i = blockIdx.x * SCAN_B + tid;
    int v = (i < n) ? cnt[i] : 0;
    s[tid] = v;
    __syncthreads();
#pragma unroll
    for (int ofs = 1; ofs < SCAN_B; ofs <<= 1) {
        int t = (tid >= ofs) ? s[tid - ofs] : 0;
        __syncthreads();
        s[tid] += t;
        __syncthreads();
    }
    if (i < n) rowptr[i] = s[tid] - v;
    if (tid == SCAN_B - 1) bsum[blockIdx.x] = s[tid];
}

__global__ void __launch_bounds__(MAXBLK) k_scan_mid(
    const int* __restrict__ bsum, int* __restrict__ boffs, int nb)
{
    __shared__ int s[MAXBLK];
    const int tid = threadIdx.x;
    int v = (tid < nb) ? bsum[tid] : 0;
    s[tid] = v;
    __syncthreads();
#pragma unroll
    for (int ofs = 1; ofs < MAXBLK; ofs <<= 1) {
        int t = (tid >= ofs) ? s[tid - ofs] : 0;
        __syncthreads();
        s[tid] += t;
        __syncthreads();
    }
    if (tid < nb) boffs[tid] = s[tid] - v;
}

__global__ void __launch_bounds__(SCAN_B) k_scan_add(
    int* __restrict__ rowptr, const int* __restrict__ boffs, int n, int E)
{
    const int i = blockIdx.x * SCAN_B + threadIdx.x;
    if (i < n) rowptr[i] += boffs[blockIdx.x];
    if (i == 0) rowptr[n] = E;
}

// ---------------- counting-sort fill ----------------

__global__ void k_fill(const int* __restrict__ row, const int* __restrict__ col,
                       const float* __restrict__ ew, const float* __restrict__ dinv,
                       const int* __restrict__ rowptr, int* __restrict__ cur,
                       int* __restrict__ srow, float* __restrict__ snorm, int E) {
    int e = blockIdx.x * blockDim.x + threadIdx.x;
    if (e >= E) return;
    int r = row[e];
    int c = col[e];
    int pos = rowptr[c] + atomicAdd(&cur[c], 1);
    srow[pos] = r;
    snorm[pos] = dinv[r] * ew[e] * dinv[c];
}

// ---------------- weight prep: single fp16 ----------------

__device__ __forceinline__ void wprep_one(const float* W, __half* dst, int idx) {
    int n = idx >> 7, k = idx & 127;
    dst[n * 128 + k] = __float2half_rn(W[k * 128 + n]);   // B[n][k] = W[k][n]
}

__global__ void k_wprep(const float* __restrict__ W, __half* __restrict__ dst) {
    int idx = blockIdx.x * blockDim.x + threadIdx.x;
    if (idx >= 16384) return;
    wprep_one(W, dst, idx);
}

__global__ void k_wprep4(const float* __restrict__ W1, const float* __restrict__ W2,
                         const float* __restrict__ W3, const float* __restrict__ W4,
                         __half* __restrict__ base) {
    int idx = blockIdx.x * blockDim.x + threadIdx.x;
    if (idx >= 16384) return;
    const float* W = (blockIdx.y == 0) ? W1 : (blockIdx.y == 1) ? W2
                   : (blockIdx.y == 2) ? W3 : W4;
    wprep_one(W, base + (blockIdx.y + 1) * 16384, idx);
}

// ---------------- fp16 HMMA GEMM: C = A @ W ----------------
// A fp16 (16KB), W fp16 (32KB); 8 mma / 4 ldsm per k-step; 3 CTAs/SM.

__global__ void __launch_bounds__(256, 3) k_gemm_mma(
    const __half* __restrict__ A, const __half* __restrict__ w16,
    const float* __restrict__ bias, __half* __restrict__ Ch,
    float* __restrict__ Cf, int M, int outFloat)
{
    extern __shared__ char sm[];
    char* sA = sm;                    // 16KB
    char* sW = sm + 16384;            // 32KB

    const int tid = threadIdx.x;
    const int wid = tid >> 5;
    const int lane = tid & 31;
    const int rbase = blockIdx.x * BM;

    const uint32_t uA = smem_u32(sA);
    const uint32_t uW = smem_u32(sW);

    for (int i = tid; i < 2048; i += 256) {
        int r = i >> 4, c = i & 15;
        uint32_t doff = (uint32_t)((r << 8) + ((c ^ (r & 7)) << 4));
        cp16(uW + doff, w16 + r * 128 + c * 8);
    }
    for (int i = tid; i < 1024; i += 256) {
        int r = i >> 4, c = i & 15;
        int grow = rbase + r;
        if (grow < M) {
            uint32_t doff = (uint32_t)((r << 8) + ((c ^ (r & 7)) << 4));
            cp16(uA + doff, A + (size_t)grow * FDIM + c * 8);
        }
    }
    asm volatile("cp.async.commit_group;" ::: "memory");
    asm volatile("cp.async.wait_group 0;" ::: "memory");
    __syncthreads();

    const int warpRow = (wid & 1) * 32;
    const int warpCol = (wid >> 1) * 32;
    const int a_r = lane & 15;
    const int a_k = (lane >> 4) << 3;
    const int b_n = (lane & 7) + ((lane >> 4) << 3);
    const int b_k = ((lane >> 3) & 1) << 3;

    float c[2][4][4];
#pragma unroll
    for (int mi = 0; mi < 2; mi++)
#pragma unroll
        for (int ni = 0; ni < 4; ni++)
#pragma unroll
            for (int q = 0; q < 4; q++) c[mi][ni][q] = 0.0f;

    uint32_t a0[2][4], a1[2][4], b0[2][4], b1[2][4];

#define LOADK(buf, k0)                                                          \
    do {                                                                        \
        ldsm4(a0[buf][0], a0[buf][1], a0[buf][2], a0[buf][3],                   \
              uA + swz(warpRow + a_r,      (k0) + a_k));                        \
        ldsm4(a1[buf][0], a1[buf][1], a1[buf][2], a1[buf][3],                   \
              uA + swz(warpRow + 16 + a_r, (k0) + a_k));                        \
        ldsm4(b0[buf][0], b0[buf][1], b0[buf][2], b0[buf][3],                   \
              uW + swz(warpCol + b_n,      (k0) + b_k));                        \
        ldsm4(b1[buf][0], b1[buf][1], b1[buf][2], b1[buf][3],                   \
              uW + swz(warpCol + 16 + b_n, (k0) + b_k));                        \
    } while (0)

    LOADK(0, 0);
#pragma unroll
    for (int it = 0; it < 8; it++) {
        const int cur = it & 1, nxt = cur ^ 1;
        if (it < 7) LOADK(nxt, (it + 1) << 4);
        mma16816h(c[0][0], a0[cur], b0[cur][0], b0[cur][1]);
        mma16816h(c[0][1], a0[cur], b0[cur][2], b0[cur][3]);
        mma16816h(c[0][2], a0[cur], b1[cur][0], b1[cur][1]);
        mma16816h(c[0][3], a0[cur], b1[cur][2], b1[cur][3]);
        mma16816h(c[1][0], a1[cur], b0[cur][0], b0[cur][1]);
        mma16816h(c[1][1], a1[cur], b0[cur][2], b0[cur][3]);
        mma16816h(c[1][2], a1[cur], b1[cur][0], b1[cur][1]);
        mma16816h(c[1][3], a1[cur], b1[cur][2], b1[cur][3]);
    }
#undef LOADK

    const int crow = lane >> 2;
    const int ccol = (lane & 3) * 2;
#pragma unroll
    for (int mi = 0; mi < 2; mi++) {
#pragma unroll
        for (int ni = 0; ni < 4; ni++) {
            int colg = warpCol + ni * 8 + ccol;
            int r0 = rbase + warpRow + mi * 16 + crow;
            int r1 = r0 + 8;
            if (outFloat) {
                float bx = bias[colg], by = bias[colg + 1];
                if (r0 < M) {
                    float2 v = make_float2(c[mi][ni][0] + bx, c[mi][ni][1] + by);
                    *reinterpret_cast<float2*>(Cf + (size_t)r0 * FDIM + colg) = v;
                }
                if (r1 < M) {
                    float2 v = make_float2(c[mi][ni][2] + bx, c[mi][ni][3] + by);
                    *reinterpret_cast<float2*>(Cf + (size_t)r1 * FDIM + colg) = v;
                }
            } else {
                if (r0 < M) {
                    __half2 v = __floats2half2_rn(c[mi][ni][0], c[mi][ni][1]);
                    *reinterpret_cast<__half2*>(Ch + (size_t)r0 * FDIM + colg) = v;
                }
                if (r1 < M) {
                    __half2 v = __floats2half2_rn(c[mi][ni][2], c[mi][ni][3]);
                    *reinterpret_cast<__half2*>(Ch + (size_t)r1 * FDIM + colg) = v;
                }
            }
        }
    }
}

// ---------------- CSR aggregate: fp16 gathers -> fp16 out ----------------

__global__ void __launch_bounds__(256) k_aggregate(
    const int* __restrict__ rowptr, const int* __restrict__ srow,
    const float* __restrict__ snorm, const float* __restrict__ dinv,
    const float* __restrict__ bias, const __half* __restrict__ t16,
    __half* __restrict__ h16, int n, int doRelu)
{
    int node = blockIdx.x * 8 + (threadIdx.x >> 5);
    if (node >= n) return;
    const int lane = threadIdx.x & 31;
    const int f4 = lane * 4;

    float d = __ldg(dinv + node);
    float d2 = d * d;

    uint2 sraw = *reinterpret_cast<const uint2*>(t16 + (size_t)node * FDIM + f4);
    float2 s0 = __half22float2(*reinterpret_cast<__half2*>(&sraw.x));
    float2 s1 = __half22float2(*reinterpret_cast<__half2*>(&sraw.y));
    float4 bv = *reinterpret_cast<const float4*>(bias + f4);
    float4 acc;
    acc.x = fmaf(s0.x, d2, bv.x);
    acc.y = fmaf(s0.y, d2, bv.y);
    acc.z = fmaf(s1.x, d2, bv.z);
    acc.w = fmaf(s1.y, d2, bv.w);

    int j = __ldg(rowptr + node);
    const int jend = __ldg(rowptr + node + 1);

#define GATHER(rj, wj)                                                          \
    do {                                                                        \
        uint2 raw = *reinterpret_cast<const uint2*>(t16 + (size_t)(rj) * FDIM + f4); \
        float2 p0 = __half22float2(*reinterpret_cast<__half2*>(&raw.x));        \
        float2 p1 = __half22float2(*reinterpret_cast<__half2*>(&raw.y));        \
        acc.x = fmaf(p0.x, (wj), acc.x); acc.y = fmaf(p0.y, (wj), acc.y);       \
        acc.z = fmaf(p1.x, (wj), acc.z); acc.w = fmaf(p1.y, (wj), acc.w);       \
    } while (0)

    for (; j + 3 < jend; j += 4) {
        int r0 = __ldg(srow + j);
        int r1 = __ldg(srow + j + 1);
        int r2 = __ldg(srow + j + 2);
        int r3 = __ldg(srow + j + 3);
        float w0 = __ldg(snorm + j);
        float w1 = __ldg(snorm + j + 1);
        float w2 = __ldg(snorm + j + 2);
        float w3 = __ldg(snorm + j + 3);
        GATHER(r0, w0);
        GATHER(r1, w1);
        GATHER(r2, w2);
        GATHER(r3, w3);
    }
    for (; j < jend; j++) {
        int r0 = __ldg(srow + j);
        float w0 = __ldg(snorm + j);
        GATHER(r0, w0);
    }
#undef GATHER

    if (doRelu) {
        acc.x = fmaxf(acc.x, 0.f); acc.y = fmaxf(acc.y, 0.f);
        acc.z = fmaxf(acc.z, 0.f); acc.w = fmaxf(acc.w, 0.f);
    }
    __half2 o0 = __floats2half2_rn(acc.x, acc.y);
    __half2 o1 = __floats2half2_rn(acc.z, acc.w);
    uint2 o;
    o.x = *reinterpret_cast<uint32_t*>(&o0);
    o.y = *reinterpret_cast<uint32_t*>(&o1);
    *reinterpret_cast<uint2*>(h16 + (size_t)node * FDIM + f4) = o;
}

// ---------------- launch ----------------

extern "C" void kernel_launch(void* const* d_in, const int* in_sizes, int n_in,
                              void* d_out, int out_size) {
    const float* x    = (const float*)d_in[0];
    const int*   ei   = (const int*)  d_in[1];
    const float* ew   = (const float*)d_in[2];
    const float* Wc[4] = {(const float*)d_in[3], (const float*)d_in[5],
                          (const float*)d_in[7], (const float*)d_in[9]};
    const float* bc[4] = {(const float*)d_in[4], (const float*)d_in[6],
                          (const float*)d_in[8], (const float*)d_in[10]};
    const float* Wout = (const float*)d_in[11];
    const float* bout = (const float*)d_in[12];
    float* out = (float*)d_out;

    const int N = in_sizes[0] / FDIM;
    const int E = in_sizes[2];
    const int* rowp = ei;
    const int* colp = ei + E;

    float *deg, *dinv, *snorm;
    int *cnt, *rowptr, *cur, *srow, *bsum, *boffs;
    __half *t16, *h16, *x16, *w16;
    cudaGetSymbolAddress((void**)&t16, g_t16);
    cudaGetSymbolAddress((void**)&h16, g_h16);
    cudaGetSymbolAddress((void**)&x16, g_x16);
    cudaGetSymbolAddress((void**)&deg, g_deg);
    cudaGetSymbolAddress((void**)&dinv, g_dinv);
    cudaGetSymbolAddress((void**)&cnt, g_cnt);
    cudaGetSymbolAddress((void**)&rowptr, g_rowptr);
    cudaGetSymbolAddress((void**)&cur, g_cursor);
    cudaGetSymbolAddress((void**)&srow, g_srow);
    cudaGetSymbolAddress((void**)&snorm, g_snorm);
    cudaGetSymbolAddress((void**)&bsum, g_bsum);
    cudaGetSymbolAddress((void**)&boffs, g_boffs);
    cudaGetSymbolAddress((void**)&w16, g_w16);

    static const int SMEM_DYN = 49152;
    cudaFuncSetAttribute(k_gemm_mma, cudaFuncAttributeMaxDynamicSharedMemorySize, SMEM_DYN);

    static cudaStream_t s2 = nullptr;
    static cudaEvent_t eFork = nullptr, eJoin = nullptr;
    if (s2 == nullptr) {
        cudaStreamCreateWithFlags(&s2, cudaStreamNonBlocking);
        cudaEventCreateWithFlags(&eFork, cudaEventDisableTiming);
        cudaEventCreateWithFlags(&eJoin, cudaEventDisableTiming);
    }

    const int TB = 256;
    const int nScanBlk = (N + SCAN_B - 1) / SCAN_B;
    const int wpBlocks = (16384 + TB - 1) / TB;
    const int gemmBlocks = (N + BM - 1) / BM;
    const int aggBlocks  = (N + 7) / 8;
    const int xpBlocks   = (N * 32 + TB - 1) / TB;

    // ---- main stream: GEMM-0 chain (gemm is launch #4 for ncu) ----
    k_wprep<<<wpBlocks, TB>>>(Wc[0], w16);                                     // #1
    k_xprep<<<xpBlocks, TB>>>(x, x16, N * 32);                                 // #2

    cudaEventRecord(eFork, 0);
    cudaStreamWaitEvent(s2, eFork, 0);

    k_init<<<(N + TB - 1) / TB, TB, 0, s2>>>(deg, cnt, cur, N);                // #3
    k_gemm_mma<<<gemmBlocks, TB, SMEM_DYN>>>(x16, w16,
                                             nullptr, t16, nullptr, N, 0);     // #4 <- profiled
    // ---- side stream: CSR build chain ----
    k_deg_hist<<<(E + TB - 1) / TB, TB, 0, s2>>>(colp, ew, deg, cnt, E);
    k_dinv<<<(N + TB - 1) / TB, TB, 0, s2>>>(deg, dinv, N);
    k_scan_local<<<nScanBlk, SCAN_B, 0, s2>>>(cnt, rowptr, bsum, N);
    k_scan_mid<<<1, MAXBLK, 0, s2>>>(bsum, boffs, nScanBlk);
    k_scan_add<<<nScanBlk, SCAN_B, 0, s2>>>(rowptr, boffs, N, E);
    k_fill<<<(E + TB - 1) / TB, TB, 0, s2>>>(rowp, colp, ew, dinv, rowptr,
                                             cur, srow, snorm, E);
    {
        dim3 wg(wpBlocks, 4);
        k_wprep4<<<wg, TB, 0, s2>>>(Wc[1], Wc[2], Wc[3], Wout, w16);
    }
    cudaEventRecord(eJoin, s2);
    cudaStreamWaitEvent(0, eJoin, 0);

    // ---- layers ----
    k_aggregate<<<aggBlocks, TB>>>(rowptr, srow, snorm, dinv, bc[0], t16,
                                   h16, N, 1);
    for (int l = 1; l < 4; l++) {
        k_gemm_mma<<<gemmBlocks, TB, SMEM_DYN>>>(h16, w16 + l * 16384,
                                                 nullptr, t16, nullptr, N, 0);
        k_aggregate<<<aggBlocks, TB>>>(rowptr, srow, snorm, dinv, bc[l], t16,
                                       h16, N, (l < 3) ? 1 : 0);
    }

    k_gemm_mma<<<gemmBlocks, TB, SMEM_DYN>>>(h16, w16 + 4 * 16384,
                                             bout, nullptr, out, N, 1);
}